// round 1
// baseline (speedup 1.0000x reference)
#include <cuda_runtime.h>
#include <stdint.h>

// Problem constants
#define BATCH   32
#define NPTS    256
#define LATENT  256
#define BOOK    512
#define NCL     10
#define BN      (BATCH*NPTS)        // 8192
#define CKDIM   (NCL*BOOK)          // 5120
#define TOTALE  (BATCH*NCL*NPTS*BOOK) // 41943040

// Output layout (flattened tuple: zq, precision_q, prob, log_prob)
#define ZQ_SIZE   (BATCH*NPTS*LATENT)     // 2097152
#define PROB_OFF  (ZQ_SIZE + 1)           // 2097153
#define LP_OFF    (PROB_OFF + BATCH*NPTS*BOOK)

// PRNG semantics: 1 = jax_threefry_partitionable (JAX >= 0.4.36 default)
#define JAX_PARTITIONABLE 1

// Scratch (device globals: allocation-free rule compliant)
__device__ float g_logits_c[TOTALE];     // [b,C,n,K] per-cluster logits
__device__ float g_enc[BN*CKDIM];        // [bn, ck] encoding * c_prob
__device__ float g_zn2[BN];
__device__ float g_bn2[CKDIM];
__device__ float g_cprob[BATCH*NCL];
__device__ float g_pq[1];

// ---------------- threefry2x32 (Random123 / JAX exact) ----------------
__host__ __device__ __forceinline__ void threefry2x32(
    uint32_t k0, uint32_t k1, uint32_t x0, uint32_t x1,
    uint32_t& o0, uint32_t& o1) {
  uint32_t ks2 = 0x1BD11BDAu ^ k0 ^ k1;
  x0 += k0; x1 += k1;
#define TF_ROT(r) { x0 += x1; x1 = (x1 << (r)) | (x1 >> (32-(r))); x1 ^= x0; }
  TF_ROT(13) TF_ROT(15) TF_ROT(26) TF_ROT(6)
  x0 += k1;  x1 += ks2 + 1u;
  TF_ROT(17) TF_ROT(29) TF_ROT(16) TF_ROT(24)
  x0 += ks2; x1 += k0 + 2u;
  TF_ROT(13) TF_ROT(15) TF_ROT(26) TF_ROT(6)
  x0 += k0;  x1 += k1 + 3u;
  TF_ROT(17) TF_ROT(29) TF_ROT(16) TF_ROT(24)
  x0 += k1;  x1 += ks2 + 4u;
  TF_ROT(13) TF_ROT(15) TF_ROT(26) TF_ROT(6)
  x0 += ks2; x1 += k0 + 5u;
#undef TF_ROT
  o0 = x0; o1 = x1;
}

__device__ __forceinline__ float unit_from_bits(uint32_t bits) {
  // jax.random.uniform: (bits>>9)|0x3f800000 as float in [1,2) minus 1
  return __uint_as_float((bits >> 9) | 0x3f800000u) - 1.0f;
}

__device__ __forceinline__ float gumbel_from_bits(uint32_t bits) {
  float u = unit_from_bits(bits);
  return -logf(-logf(u + 1e-10f) + 1e-10f);
}

// bits for flat index j under the chosen PRNG semantics
__device__ __forceinline__ uint32_t rand_bits(uint32_t ke0, uint32_t ke1, uint32_t j) {
#if JAX_PARTITIONABLE
  uint32_t o0, o1;
  threefry2x32(ke0, ke1, 0u, j, o0, o1);
  return o0 ^ o1;
#else
  // legacy: handled by callers via pairing (not used in this build)
  return 0u;
#endif
}

// ---------------- K0: precision scalars + cluster gumbel-softmax ----------------
__global__ void k0_cprob(const float* __restrict__ c_logits,
                         const float* __restrict__ lpq,
                         const float* __restrict__ lpqc,
                         float* __restrict__ d_out,
                         uint32_t kc0, uint32_t kc1) {
  __shared__ float gsh[BATCH*NCL];
  int t = threadIdx.x;
  if (t < BATCH*NCL) {
    gsh[t] = gumbel_from_bits(rand_bits(kc0, kc1, (uint32_t)t));
  }
  float pq  = 0.5f / fmaxf(1.0f + expf(lpq[0]),  1e-10f);
  float pqc = 0.5f / fmaxf(1.0f + expf(lpqc[0]), 1e-10f);
  if (t == 0) { g_pq[0] = pq; d_out[ZQ_SIZE] = pq; }
  __syncthreads();
  if (t < BATCH) {
    float y[NCL];
    float m = -3.4e38f;
#pragma unroll
    for (int c = 0; c < NCL; c++) {
      y[c] = (c_logits[t*NCL + c] * pqc + gsh[t*NCL + c]) * 2.0f; // /T, T=0.5
      m = fmaxf(m, y[c]);
    }
    float s = 0.f;
#pragma unroll
    for (int c = 0; c < NCL; c++) { y[c] = expf(y[c] - m); s += y[c]; }
    float inv = 1.0f / s;
#pragma unroll
    for (int c = 0; c < NCL; c++) g_cprob[t*NCL + c] = y[c] * inv;
  }
}

// ---------------- norms: |ze_row|^2 and |book_row|^2 ----------------
__global__ void k_norms(const float* __restrict__ ze, const float* __restrict__ books) {
  int warp = (blockIdx.x * blockDim.x + threadIdx.x) >> 5;
  int lane = threadIdx.x & 31;
  if (warp >= BN + CKDIM) return;
  const float* row = (warp < BN) ? (ze + (size_t)warp * LATENT)
                                 : (books + (size_t)(warp - BN) * LATENT);
  float s = 0.f;
#pragma unroll 4
  for (int d = lane; d < LATENT; d += 32) { float v = row[d]; s += v * v; }
#pragma unroll
  for (int o = 16; o; o >>= 1) s += __shfl_xor_sync(0xffffffffu, s, o);
  if (lane == 0) {
    if (warp < BN) g_zn2[warp] = s; else g_bn2[warp - BN] = s;
  }
}

// ---------------- GEMM1: logits_c = -(|z|^2 + |b|^2 - 2 z.b) * pq ----------------
// C[8192, 5120] from A=ze[8192,256], B=books[5120,256] (both K-major, K=256)
__global__ __launch_bounds__(256) void k_gemm1(const float* __restrict__ ze,
                                               const float* __restrict__ books) {
  __shared__ float As[32][65];
  __shared__ float Bs[32][65];
  int mb = blockIdx.x * 64;
  int nb = blockIdx.y * 64;
  int t = threadIdx.x;
  int tx = t & 15, ty = t >> 4;
  float acc[4][4] = {};
  float pq = g_pq[0];

  for (int d0 = 0; d0 < LATENT; d0 += 32) {
#pragma unroll
    for (int it = 0; it < 8; it++) {
      int e = it * 256 + t;
      int mm = e >> 5, dd = e & 31;
      As[dd][mm] = ze[(size_t)(mb + mm) * LATENT + d0 + dd];
      Bs[dd][mm] = books[(size_t)(nb + mm) * LATENT + d0 + dd];
    }
    __syncthreads();
#pragma unroll
    for (int dd = 0; dd < 32; dd++) {
      float a0 = As[dd][ty*4+0], a1 = As[dd][ty*4+1];
      float a2 = As[dd][ty*4+2], a3 = As[dd][ty*4+3];
      float b0 = Bs[dd][tx*4+0], b1 = Bs[dd][tx*4+1];
      float b2 = Bs[dd][tx*4+2], b3 = Bs[dd][tx*4+3];
      acc[0][0] += a0*b0; acc[0][1] += a0*b1; acc[0][2] += a0*b2; acc[0][3] += a0*b3;
      acc[1][0] += a1*b0; acc[1][1] += a1*b1; acc[1][2] += a1*b2; acc[1][3] += a1*b3;
      acc[2][0] += a2*b0; acc[2][1] += a2*b1; acc[2][2] += a2*b2; acc[2][3] += a2*b3;
      acc[3][0] += a3*b0; acc[3][1] += a3*b1; acc[3][2] += a3*b2; acc[3][3] += a3*b3;
    }
    __syncthreads();
  }
#pragma unroll
  for (int i = 0; i < 4; i++) {
    int m = mb + ty*4 + i;
    int b = m >> 8, n = m & 255;
    float zn = g_zn2[m];
#pragma unroll
    for (int j = 0; j < 4; j++) {
      int col = nb + tx*4 + j;
      int c = col >> 9, k = col & 511;
      float v = -(zn + g_bn2[col] - 2.0f * acc[i][j]) * pq;
      g_logits_c[((b*NCL + c)*NPTS + n)*BOOK + k] = v;
    }
  }
}

// ---------------- block reductions ----------------
template<bool IS_MAX>
__device__ __forceinline__ float blockReduce(float v, float* red) {
#pragma unroll
  for (int o = 16; o; o >>= 1) {
    float x = __shfl_xor_sync(0xffffffffu, v, o);
    v = IS_MAX ? fmaxf(v, x) : (v + x);
  }
  int w = threadIdx.x >> 5;
  __syncthreads();                 // protect scratch from prior use
  if ((threadIdx.x & 31) == 0) red[w] = v;
  __syncthreads();
  float r = red[0];
#pragma unroll
  for (int i = 1; i < 8; i++) r = IS_MAX ? fmaxf(r, red[i]) : (r + red[i]);
  return r;
}

// ---------------- K2: gumbel-softmax encoding + weighted-logit softmax ----------------
// grid (32, 256): one block per (b, n) row; 256 threads, 2 k's each.
__global__ __launch_bounds__(256) void k2_encode(float* __restrict__ d_out,
                                                 uint32_t ke0, uint32_t ke1) {
  int b = blockIdx.x, n = blockIdx.y;
  int t = threadIdx.x;
  __shared__ float wacc[BOOK];
  __shared__ float red[8];
  __shared__ float cp[NCL];
  if (t < NCL) cp[t] = g_cprob[b*NCL + t];
  wacc[t] = 0.f; wacc[t + 256] = 0.f;
  __syncthreads();

  for (int c = 0; c < NCL; c++) {
    float cpc = cp[c];
    float L[2], y[2];
#pragma unroll
    for (int h = 0; h < 2; h++) {
      int k = t + 256*h;
      int j = ((b*NCL + c)*NPTS + n)*BOOK + k;
      float g = gumbel_from_bits(rand_bits(ke0, ke1, (uint32_t)j));
      L[h] = g_logits_c[j];
      y[h] = (L[h] + g) * 2.0f;          // /T, T=0.5
    }
    float m = blockReduce<true >(fmaxf(y[0], y[1]), red);
    float e0 = expf(y[0] - m), e1 = expf(y[1] - m);
    float s = blockReduce<false>(e0 + e1, red);
    float r = cpc / s;
    int enc_base = (b*NPTS + n)*CKDIM + c*BOOK;
    g_enc[enc_base + t]       = e0 * r;
    g_enc[enc_base + t + 256] = e1 * r;
    wacc[t]       += L[0] * cpc;
    wacc[t + 256] += L[1] * cpc;
  }
  __syncthreads();

  float w0 = wacc[t], w1 = wacc[t + 256];
  float m = blockReduce<true >(fmaxf(w0, w1), red);
  float e0 = expf(w0 - m), e1 = expf(w1 - m);
  float s = blockReduce<false>(e0 + e1, red);
  float inv = 1.0f / s, ls = logf(s);
  int base = (b*NPTS + n)*BOOK;
  d_out[PROB_OFF + base + t]       = e0 * inv;
  d_out[PROB_OFF + base + t + 256] = e1 * inv;
  d_out[LP_OFF   + base + t]       = (w0 - m) - ls;
  d_out[LP_OFF   + base + t + 256] = (w1 - m) - ls;
}

// ---------------- GEMM2: zq[8192,256] = enc'[8192,5120] @ books[5120,256] ----------------
__global__ __launch_bounds__(256) void k_gemm2(const float* __restrict__ books,
                                               float* __restrict__ d_out) {
  __shared__ float As[32][65];
  __shared__ float Bs[32][65];
  int mb = blockIdx.x * 64;
  int nb = blockIdx.y * 64;
  int t = threadIdx.x;
  int tx = t & 15, ty = t >> 4;
  float acc[4][4] = {};

  for (int k0 = 0; k0 < CKDIM; k0 += 32) {
#pragma unroll
    for (int it = 0; it < 8; it++) {
      int e = it * 256 + t;
      { int mm = e >> 5, kk = e & 31;
        As[kk][mm] = g_enc[(size_t)(mb + mm) * CKDIM + k0 + kk]; }
      { int nn = e & 63, kk = e >> 6;
        Bs[kk][nn] = books[(size_t)(k0 + kk) * LATENT + nb + nn]; }
    }
    __syncthreads();
#pragma unroll
    for (int kk = 0; kk < 32; kk++) {
      float a0 = As[kk][ty*4+0], a1 = As[kk][ty*4+1];
      float a2 = As[kk][ty*4+2], a3 = As[kk][ty*4+3];
      float b0 = Bs[kk][tx*4+0], b1 = Bs[kk][tx*4+1];
      float b2 = Bs[kk][tx*4+2], b3 = Bs[kk][tx*4+3];
      acc[0][0] += a0*b0; acc[0][1] += a0*b1; acc[0][2] += a0*b2; acc[0][3] += a0*b3;
      acc[1][0] += a1*b0; acc[1][1] += a1*b1; acc[1][2] += a1*b2; acc[1][3] += a1*b3;
      acc[2][0] += a2*b0; acc[2][1] += a2*b1; acc[2][2] += a2*b2; acc[2][3] += a2*b3;
      acc[3][0] += a3*b0; acc[3][1] += a3*b1; acc[3][2] += a3*b2; acc[3][3] += a3*b3;
    }
    __syncthreads();
  }
#pragma unroll
  for (int i = 0; i < 4; i++) {
    int m = mb + ty*4 + i;
#pragma unroll
    for (int j = 0; j < 4; j++) {
      int col = nb + tx*4 + j;
      d_out[(size_t)m * LATENT + col] = acc[i][j];   // zq at offset 0
    }
  }
}

// ---------------- launch ----------------
extern "C" void kernel_launch(void* const* d_in, const int* in_sizes, int n_in,
                              void* d_out_v, int out_size) {
  (void)in_sizes; (void)n_in; (void)out_size;
  const float* ze       = (const float*)d_in[0];
  const float* c_logits = (const float*)d_in[1];
  const float* books    = (const float*)d_in[2];
  const float* lpq      = (const float*)d_in[3];
  const float* lpqc     = (const float*)d_in[4];
  float* d_out = (float*)d_out_v;

  // jax.random.key(42) -> (0, 42); split(key) under partitionable semantics:
  //   kc = threefry(key, (0,0)), ke = threefry(key, (0,1))
  uint32_t kc0, kc1, ke0, ke1;
  threefry2x32(0u, 42u, 0u, 0u, kc0, kc1);
  threefry2x32(0u, 42u, 0u, 1u, ke0, ke1);

  k0_cprob<<<1, 320>>>(c_logits, lpq, lpqc, d_out, kc0, kc1);
  {
    int rows = BN + CKDIM;                 // 13312 rows, 1 warp each
    int blocks = (rows + 7) / 8;           // 8 warps per 256-thread block
    k_norms<<<blocks, 256>>>(ze, books);
  }
  k_gemm1<<<dim3(BN/64, CKDIM/64), 256>>>(ze, books);
  k2_encode<<<dim3(BATCH, NPTS), 256>>>(d_out, ke0, ke1);
  k_gemm2<<<dim3(BN/64, LATENT/64), 256>>>(books, d_out);
}

// round 2
// speedup vs baseline: 1.2243x; 1.2243x over previous
#include <cuda_runtime.h>
#include <stdint.h>

// Problem constants
#define BATCH   32
#define NPTS    256
#define LATENT  256
#define BOOK    512
#define NCL     10
#define BN      (BATCH*NPTS)          // 8192
#define CKDIM   (NCL*BOOK)            // 5120
#define TOTALE  (BATCH*NCL*NPTS*BOOK) // 41943040

// Output layout (flattened tuple: zq, precision_q, prob, log_prob)
#define ZQ_SIZE   (BATCH*NPTS*LATENT)     // 2097152
#define PROB_OFF  (ZQ_SIZE + 1)           // 2097153
#define LP_OFF    (PROB_OFF + BATCH*NPTS*BOOK)

// Scratch (device globals: allocation-free rule compliant)
__device__ __align__(16) float g_logits_c[TOTALE];   // [b,C,n,K]
__device__ __align__(16) float g_enc[BN*CKDIM];      // [bn, ck] encoding * c_prob
__device__ __align__(16) float g_zn2[BN];
__device__ __align__(16) float g_bn2[CKDIM];
__device__ float g_cprob[BATCH*NCL];
__device__ float g_pq[1];

// ---------------- packed f32x2 FMA (sm_100+ FFMA2) ----------------
__device__ __forceinline__ void ffma2(unsigned long long& d,
                                      unsigned long long a,
                                      unsigned long long b) {
  asm("fma.rn.f32x2 %0, %1, %2, %0;" : "+l"(d) : "l"(a), "l"(b));
}
__device__ __forceinline__ float2 unpack2(unsigned long long v) {
  float2 r;
  asm("mov.b64 {%0, %1}, %2;" : "=f"(r.x), "=f"(r.y) : "l"(v));
  return r;
}

// ---------------- threefry2x32 (Random123 / JAX exact) ----------------
__host__ __device__ __forceinline__ void threefry2x32(
    uint32_t k0, uint32_t k1, uint32_t x0, uint32_t x1,
    uint32_t& o0, uint32_t& o1) {
  uint32_t ks2 = 0x1BD11BDAu ^ k0 ^ k1;
  x0 += k0; x1 += k1;
#define TF_ROT(r) { x0 += x1; x1 = (x1 << (r)) | (x1 >> (32-(r))); x1 ^= x0; }
  TF_ROT(13) TF_ROT(15) TF_ROT(26) TF_ROT(6)
  x0 += k1;  x1 += ks2 + 1u;
  TF_ROT(17) TF_ROT(29) TF_ROT(16) TF_ROT(24)
  x0 += ks2; x1 += k0 + 2u;
  TF_ROT(13) TF_ROT(15) TF_ROT(26) TF_ROT(6)
  x0 += k0;  x1 += k1 + 3u;
  TF_ROT(17) TF_ROT(29) TF_ROT(16) TF_ROT(24)
  x0 += k1;  x1 += ks2 + 4u;
  TF_ROT(13) TF_ROT(15) TF_ROT(26) TF_ROT(6)
  x0 += ks2; x1 += k0 + 5u;
#undef TF_ROT
  o0 = x0; o1 = x1;
}

__device__ __forceinline__ float unit_from_bits(uint32_t bits) {
  return __uint_as_float((bits >> 9) | 0x3f800000u) - 1.0f;
}
__device__ __forceinline__ float gumbel_from_bits(uint32_t bits) {
  float u = unit_from_bits(bits);
  return -__logf(-__logf(u + 1e-10f) + 1e-10f);
}
__device__ __forceinline__ uint32_t rand_bits(uint32_t k0, uint32_t k1, uint32_t j) {
  uint32_t o0, o1;
  threefry2x32(k0, k1, 0u, j, o0, o1);
  return o0 ^ o1;
}

// ---------------- K0: precision scalars + cluster gumbel-softmax ----------------
__global__ void k0_cprob(const float* __restrict__ c_logits,
                         const float* __restrict__ lpq,
                         const float* __restrict__ lpqc,
                         float* __restrict__ d_out,
                         uint32_t kc0, uint32_t kc1) {
  __shared__ float gsh[BATCH*NCL];
  int t = threadIdx.x;
  if (t < BATCH*NCL) gsh[t] = gumbel_from_bits(rand_bits(kc0, kc1, (uint32_t)t));
  float pq  = 0.5f / fmaxf(1.0f + expf(lpq[0]),  1e-10f);
  float pqc = 0.5f / fmaxf(1.0f + expf(lpqc[0]), 1e-10f);
  if (t == 0) { g_pq[0] = pq; d_out[ZQ_SIZE] = pq; }
  __syncthreads();
  if (t < BATCH) {
    float y[NCL];
    float m = -3.4e38f;
#pragma unroll
    for (int c = 0; c < NCL; c++) {
      y[c] = (c_logits[t*NCL + c] * pqc + gsh[t*NCL + c]) * 2.0f;
      m = fmaxf(m, y[c]);
    }
    float s = 0.f;
#pragma unroll
    for (int c = 0; c < NCL; c++) { y[c] = expf(y[c] - m); s += y[c]; }
    float inv = 1.0f / s;
#pragma unroll
    for (int c = 0; c < NCL; c++) g_cprob[t*NCL + c] = y[c] * inv;
  }
}

// ---------------- norms ----------------
__global__ void k_norms(const float* __restrict__ ze, const float* __restrict__ books) {
  int warp = (blockIdx.x * blockDim.x + threadIdx.x) >> 5;
  int lane = threadIdx.x & 31;
  if (warp >= BN + CKDIM) return;
  const float* row = (warp < BN) ? (ze + (size_t)warp * LATENT)
                                 : (books + (size_t)(warp - BN) * LATENT);
  float s = 0.f;
#pragma unroll 4
  for (int d = lane; d < LATENT; d += 32) { float v = row[d]; s += v * v; }
#pragma unroll
  for (int o = 16; o; o >>= 1) s += __shfl_xor_sync(0xffffffffu, s, o);
  if (lane == 0) { if (warp < BN) g_zn2[warp] = s; else g_bn2[warp - BN] = s; }
}

// ---------------- GEMM1 (FFMA2): 64(M) x 128(N) tile, Kt=32 ----------------
// C[8192,5120]: A=ze[8192,256] K-major, B=books[5120,256] K-major.
// Thread (tx,ty) in 16x16: rows m=ty*4+i, col-pairs n = tx*2 + 32*j.
#define SA1 130   // As_dup row stride (floats): 128 data + 2 pad (stride%32==2)
#define SB1 130   // Bs row stride
__global__ __launch_bounds__(256) void k_gemm1(const float* __restrict__ ze,
                                               const float* __restrict__ books) {
  __shared__ __align__(16) float As[32*SA1];  // As[kk*SA1 + 2*m + h] (dup)
  __shared__ __align__(16) float Bs[32*SB1];  // Bs[kk*SB1 + n]
  int mb = blockIdx.x * 64, nb = blockIdx.y * 128;
  int t = threadIdx.x, tx = t & 15, ty = t >> 4;
  unsigned long long acc[4][4];
#pragma unroll
  for (int i = 0; i < 4; i++)
#pragma unroll
    for (int j = 0; j < 4; j++) acc[i][j] = 0ull;
  float pq = g_pq[0];

  for (int k0 = 0; k0 < LATENT; k0 += 32) {
#pragma unroll
    for (int it = 0; it < 8; it++) {            // A: 64m x 32k
      int idx = it*256 + t, m = idx >> 5, kk = idx & 31;
      float v = ze[(size_t)(mb + m) * LATENT + k0 + kk];
      *(float2*)&As[kk*SA1 + 2*m] = make_float2(v, v);
    }
#pragma unroll
    for (int it = 0; it < 16; it++) {           // B: 128n x 32k
      int idx = it*256 + t, n = idx >> 5, kk = idx & 31;
      Bs[kk*SB1 + n] = books[(size_t)(nb + n) * LATENT + k0 + kk];
    }
    __syncthreads();
#pragma unroll
    for (int kk = 0; kk < 32; kk++) {
      unsigned long long a0 = *(unsigned long long*)&As[kk*SA1 + 2*(ty*4+0)];
      unsigned long long a1 = *(unsigned long long*)&As[kk*SA1 + 2*(ty*4+1)];
      unsigned long long a2 = *(unsigned long long*)&As[kk*SA1 + 2*(ty*4+2)];
      unsigned long long a3 = *(unsigned long long*)&As[kk*SA1 + 2*(ty*4+3)];
      unsigned long long b0 = *(unsigned long long*)&Bs[kk*SB1 + tx*2 +  0];
      unsigned long long b1 = *(unsigned long long*)&Bs[kk*SB1 + tx*2 + 32];
      unsigned long long b2 = *(unsigned long long*)&Bs[kk*SB1 + tx*2 + 64];
      unsigned long long b3 = *(unsigned long long*)&Bs[kk*SB1 + tx*2 + 96];
      ffma2(acc[0][0], a0, b0); ffma2(acc[0][1], a0, b1);
      ffma2(acc[0][2], a0, b2); ffma2(acc[0][3], a0, b3);
      ffma2(acc[1][0], a1, b0); ffma2(acc[1][1], a1, b1);
      ffma2(acc[1][2], a1, b2); ffma2(acc[1][3], a1, b3);
      ffma2(acc[2][0], a2, b0); ffma2(acc[2][1], a2, b1);
      ffma2(acc[2][2], a2, b2); ffma2(acc[2][3], a2, b3);
      ffma2(acc[3][0], a3, b0); ffma2(acc[3][1], a3, b1);
      ffma2(acc[3][2], a3, b2); ffma2(acc[3][3], a3, b3);
    }
    __syncthreads();
  }
#pragma unroll
  for (int i = 0; i < 4; i++) {
    int m = mb + ty*4 + i;
    int b = m >> 8, n = m & 255;
    float zn = g_zn2[m];
#pragma unroll
    for (int j = 0; j < 4; j++) {
      int col = nb + tx*2 + 32*j;             // even; pair within one cluster
      int c = col >> 9, k = col & 511;
      float2 dot = unpack2(acc[i][j]);
      float2 bn  = *(const float2*)&g_bn2[col];
      float2 out;
      out.x = -(zn + bn.x - 2.0f*dot.x) * pq;
      out.y = -(zn + bn.y - 2.0f*dot.y) * pq;
      *(float2*)&g_logits_c[(((size_t)(b*NCL + c))*NPTS + n)*BOOK + k] = out;
    }
  }
}

// ---------------- block reductions ----------------
template<bool IS_MAX>
__device__ __forceinline__ float blockReduce(float v, float* red) {
#pragma unroll
  for (int o = 16; o; o >>= 1) {
    float x = __shfl_xor_sync(0xffffffffu, v, o);
    v = IS_MAX ? fmaxf(v, x) : (v + x);
  }
  int w = threadIdx.x >> 5;
  __syncthreads();
  if ((threadIdx.x & 31) == 0) red[w] = v;
  __syncthreads();
  float r = red[0];
#pragma unroll
  for (int i = 1; i < 8; i++) r = IS_MAX ? fmaxf(r, red[i]) : (r + red[i]);
  return r;
}

// ---------------- K2: gumbel-softmax encoding + weighted-logit softmax ----------------
__global__ __launch_bounds__(256) void k2_encode(float* __restrict__ d_out,
                                                 uint32_t ke0, uint32_t ke1) {
  int b = blockIdx.x, n = blockIdx.y;
  int t = threadIdx.x;
  __shared__ float wacc[BOOK];
  __shared__ float red[8];
  __shared__ float cp[NCL];
  if (t < NCL) cp[t] = g_cprob[b*NCL + t];
  wacc[t] = 0.f; wacc[t + 256] = 0.f;
  __syncthreads();

  for (int c = 0; c < NCL; c++) {
    float cpc = cp[c];
    float L[2], y[2];
#pragma unroll
    for (int h = 0; h < 2; h++) {
      int k = t + 256*h;
      int j = ((b*NCL + c)*NPTS + n)*BOOK + k;
      float g = gumbel_from_bits(rand_bits(ke0, ke1, (uint32_t)j));
      L[h] = g_logits_c[j];
      y[h] = (L[h] + g) * 2.0f;
    }
    float m = blockReduce<true >(fmaxf(y[0], y[1]), red);
    float e0 = __expf(y[0] - m), e1 = __expf(y[1] - m);
    float s = blockReduce<false>(e0 + e1, red);
    float r = cpc / s;
    int enc_base = (b*NPTS + n)*CKDIM + c*BOOK;
    g_enc[enc_base + t]       = e0 * r;
    g_enc[enc_base + t + 256] = e1 * r;
    wacc[t]       += L[0] * cpc;
    wacc[t + 256] += L[1] * cpc;
  }
  __syncthreads();

  float w0 = wacc[t], w1 = wacc[t + 256];
  float m = blockReduce<true >(fmaxf(w0, w1), red);
  float e0 = __expf(w0 - m), e1 = __expf(w1 - m);
  float s = blockReduce<false>(e0 + e1, red);
  float inv = 1.0f / s, ls = __logf(s);
  int base = (b*NPTS + n)*BOOK;
  d_out[PROB_OFF + base + t]       = e0 * inv;
  d_out[PROB_OFF + base + t + 256] = e1 * inv;
  d_out[LP_OFF   + base + t]       = (w0 - m) - ls;
  d_out[LP_OFF   + base + t + 256] = (w1 - m) - ls;
}

// ---------------- GEMM2 (FFMA2): 32(M) x 128(N) tile, Kt=32 ----------------
// zq[8192,256] = g_enc[8192,5120] @ books_flat[5120,256] (N-contiguous B).
#define SA2 66    // As_dup row stride: 64 data + 2 pad (stride%32==2)
#define SB2 132   // Bs row stride: 128 data + 4 pad (even)
__global__ __launch_bounds__(256) void k_gemm2(const float* __restrict__ books,
                                               float* __restrict__ d_out) {
  __shared__ __align__(16) float As[32*SA2];  // As[kk*SA2 + 2*m + h] (dup)
  __shared__ __align__(16) float Bs[32*SB2];  // Bs[kk*SB2 + n]
  int mb = blockIdx.x * 32, nb = blockIdx.y * 128;
  int t = threadIdx.x, tx = t & 15, ty = t >> 4;
  unsigned long long acc[2][4];
#pragma unroll
  for (int i = 0; i < 2; i++)
#pragma unroll
    for (int j = 0; j < 4; j++) acc[i][j] = 0ull;

  for (int k0 = 0; k0 < CKDIM; k0 += 32) {
#pragma unroll
    for (int it = 0; it < 4; it++) {           // A: 32m x 32k
      int idx = it*256 + t, m = idx >> 5, kk = idx & 31;
      float v = g_enc[(size_t)(mb + m) * CKDIM + k0 + kk];
      *(float2*)&As[kk*SA2 + 2*m] = make_float2(v, v);
    }
#pragma unroll
    for (int it = 0; it < 16; it++) {          // B: 32k x 128n
      int idx = it*256 + t, kk = idx >> 7, n = idx & 127;
      Bs[kk*SB2 + n] = books[(size_t)(k0 + kk) * LATENT + nb + n];
    }
    __syncthreads();
#pragma unroll
    for (int kk = 0; kk < 32; kk++) {
      unsigned long long a0 = *(unsigned long long*)&As[kk*SA2 + 2*(ty*2+0)];
      unsigned long long a1 = *(unsigned long long*)&As[kk*SA2 + 2*(ty*2+1)];
      unsigned long long b0 = *(unsigned long long*)&Bs[kk*SB2 + tx*2 +  0];
      unsigned long long b1 = *(unsigned long long*)&Bs[kk*SB2 + tx*2 + 32];
      unsigned long long b2 = *(unsigned long long*)&Bs[kk*SB2 + tx*2 + 64];
      unsigned long long b3 = *(unsigned long long*)&Bs[kk*SB2 + tx*2 + 96];
      ffma2(acc[0][0], a0, b0); ffma2(acc[0][1], a0, b1);
      ffma2(acc[0][2], a0, b2); ffma2(acc[0][3], a0, b3);
      ffma2(acc[1][0], a1, b0); ffma2(acc[1][1], a1, b1);
      ffma2(acc[1][2], a1, b2); ffma2(acc[1][3], a1, b3);
    }
    __syncthreads();
  }
#pragma unroll
  for (int i = 0; i < 2; i++) {
    size_t m = mb + ty*2 + i;
#pragma unroll
    for (int j = 0; j < 4; j++) {
      int col = nb + tx*2 + 32*j;
      float2 v = unpack2(acc[i][j]);
      *(float2*)&d_out[m * LATENT + col] = v;   // zq at offset 0
    }
  }
}

// ---------------- launch ----------------
extern "C" void kernel_launch(void* const* d_in, const int* in_sizes, int n_in,
                              void* d_out_v, int out_size) {
  (void)in_sizes; (void)n_in; (void)out_size;
  const float* ze       = (const float*)d_in[0];
  const float* c_logits = (const float*)d_in[1];
  const float* books    = (const float*)d_in[2];
  const float* lpq      = (const float*)d_in[3];
  const float* lpqc     = (const float*)d_in[4];
  float* d_out = (float*)d_out_v;

  uint32_t kc0, kc1, ke0, ke1;
  threefry2x32(0u, 42u, 0u, 0u, kc0, kc1);
  threefry2x32(0u, 42u, 0u, 1u, ke0, ke1);

  k0_cprob<<<1, 320>>>(c_logits, lpq, lpqc, d_out, kc0, kc1);
  {
    int rows = BN + CKDIM;
    int blocks = (rows + 7) / 8;
    k_norms<<<blocks, 256>>>(ze, books);
  }
  k_gemm1<<<dim3(BN/64, CKDIM/128), 256>>>(ze, books);
  k2_encode<<<dim3(BATCH, NPTS), 256>>>(d_out, ke0, ke1);
  k_gemm2<<<dim3(BN/32, LATENT/128), 256>>>(books, d_out);
}

// round 4
// speedup vs baseline: 3.0923x; 2.5258x over previous
#include <cuda_runtime.h>
#include <cuda_bf16.h>
#include <stdint.h>

// Problem constants
#define BATCH   32
#define NPTS    256
#define LATENT  256
#define BOOK    512
#define NCL     10
#define BN      (BATCH*NPTS)          // 8192
#define CKDIM   (NCL*BOOK)            // 5120
#define TOTALE  (BATCH*NCL*NPTS*BOOK) // 41943040

// Output layout (flattened tuple: zq, precision_q, prob, log_prob)
#define ZQ_SIZE   (BATCH*NPTS*LATENT)     // 2097152
#define PROB_OFF  (ZQ_SIZE + 1)
#define LP_OFF    (PROB_OFF + BATCH*NPTS*BOOK)

// Scratch (device globals)
__device__ __align__(16) float g_logits_c[TOTALE];   // [b,C,n,K]
__device__ __align__(16) float g_zn2[BN];
__device__ __align__(16) float g_bn2[CKDIM];
__device__ float g_cprob[BATCH*NCL];
__device__ float g_pq[1];
// bf16 2-way splits
__device__ __align__(16) __nv_bfloat16 g_ze1[BN*LATENT];
__device__ __align__(16) __nv_bfloat16 g_ze2[BN*LATENT];
__device__ __align__(16) __nv_bfloat16 g_b1[CKDIM*LATENT];
__device__ __align__(16) __nv_bfloat16 g_b2[CKDIM*LATENT];
__device__ __align__(16) __nv_bfloat16 g_enc1[(size_t)BN*CKDIM];
__device__ __align__(16) __nv_bfloat16 g_enc2[(size_t)BN*CKDIM];

// ---------------- PTX helpers ----------------
__device__ __forceinline__ uint32_t smem_u32(const void* p) {
  uint32_t a;
  asm("{ .reg .u64 t; cvta.to.shared.u64 t, %1; cvt.u32.u64 %0, t; }" : "=r"(a) : "l"(p));
  return a;
}
__device__ __forceinline__ void ldm_x4(uint32_t r[4], uint32_t addr) {
  asm volatile("ldmatrix.sync.aligned.m8n8.x4.shared.b16 {%0,%1,%2,%3}, [%4];"
               : "=r"(r[0]), "=r"(r[1]), "=r"(r[2]), "=r"(r[3]) : "r"(addr));
}
__device__ __forceinline__ void ldm_x4_t(uint32_t r[4], uint32_t addr) {
  asm volatile("ldmatrix.sync.aligned.m8n8.x4.trans.shared.b16 {%0,%1,%2,%3}, [%4];"
               : "=r"(r[0]), "=r"(r[1]), "=r"(r[2]), "=r"(r[3]) : "r"(addr));
}
__device__ __forceinline__ void mma16816(float d[4], const uint32_t a[4],
                                         const uint32_t b0, const uint32_t b1) {
  asm volatile(
    "mma.sync.aligned.m16n8k16.row.col.f32.bf16.bf16.f32 "
    "{%0,%1,%2,%3}, {%4,%5,%6,%7}, {%8,%9}, {%0,%1,%2,%3};"
    : "+f"(d[0]), "+f"(d[1]), "+f"(d[2]), "+f"(d[3])
    : "r"(a[0]), "r"(a[1]), "r"(a[2]), "r"(a[3]), "r"(b0), "r"(b1));
}

// ---------------- threefry2x32 (JAX exact) ----------------
__host__ __device__ __forceinline__ void threefry2x32(
    uint32_t k0, uint32_t k1, uint32_t x0, uint32_t x1,
    uint32_t& o0, uint32_t& o1) {
  uint32_t ks2 = 0x1BD11BDAu ^ k0 ^ k1;
  x0 += k0; x1 += k1;
#define TF_ROT(r) { x0 += x1; x1 = (x1 << (r)) | (x1 >> (32-(r))); x1 ^= x0; }
  TF_ROT(13) TF_ROT(15) TF_ROT(26) TF_ROT(6)
  x0 += k1;  x1 += ks2 + 1u;
  TF_ROT(17) TF_ROT(29) TF_ROT(16) TF_ROT(24)
  x0 += ks2; x1 += k0 + 2u;
  TF_ROT(13) TF_ROT(15) TF_ROT(26) TF_ROT(6)
  x0 += k0;  x1 += k1 + 3u;
  TF_ROT(17) TF_ROT(29) TF_ROT(16) TF_ROT(24)
  x0 += k1;  x1 += ks2 + 4u;
  TF_ROT(13) TF_ROT(15) TF_ROT(26) TF_ROT(6)
  x0 += ks2; x1 += k0 + 5u;
#undef TF_ROT
  o0 = x0; o1 = x1;
}
__device__ __forceinline__ float unit_from_bits(uint32_t bits) {
  return __uint_as_float((bits >> 9) | 0x3f800000u) - 1.0f;
}
// Accurate inner log (rel error near u~1 corrupts gumbel-max winners);
// fast outer log (absolute error only).
__device__ __forceinline__ float gumbel_from_bits(uint32_t bits) {
  float u = unit_from_bits(bits);
  float inner = logf(u + 1e-10f);
  return -__logf(1e-10f - inner);
}
__device__ __forceinline__ uint32_t rand_bits(uint32_t k0, uint32_t k1, uint32_t j) {
  uint32_t o0, o1;
  threefry2x32(k0, k1, 0u, j, o0, o1);
  return o0 ^ o1;
}

// ---------------- K0 ----------------
__global__ void k0_cprob(const float* __restrict__ c_logits,
                         const float* __restrict__ lpq,
                         const float* __restrict__ lpqc,
                         float* __restrict__ d_out,
                         uint32_t kc0, uint32_t kc1) {
  __shared__ float gsh[BATCH*NCL];
  int t = threadIdx.x;
  if (t < BATCH*NCL) gsh[t] = gumbel_from_bits(rand_bits(kc0, kc1, (uint32_t)t));
  float pq  = 0.5f / fmaxf(1.0f + expf(lpq[0]),  1e-10f);
  float pqc = 0.5f / fmaxf(1.0f + expf(lpqc[0]), 1e-10f);
  if (t == 0) { g_pq[0] = pq; d_out[ZQ_SIZE] = pq; }
  __syncthreads();
  if (t < BATCH) {
    float y[NCL];
    float m = -3.4e38f;
#pragma unroll
    for (int c = 0; c < NCL; c++) {
      y[c] = (c_logits[t*NCL + c] * pqc + gsh[t*NCL + c]) * 2.0f;
      m = fmaxf(m, y[c]);
    }
    float s = 0.f;
#pragma unroll
    for (int c = 0; c < NCL; c++) { y[c] = expf(y[c] - m); s += y[c]; }
    float inv = 1.0f / s;
#pragma unroll
    for (int c = 0; c < NCL; c++) g_cprob[t*NCL + c] = y[c] * inv;
  }
}

// ---------------- norms ----------------
__global__ void k_norms(const float* __restrict__ ze, const float* __restrict__ books) {
  int warp = (blockIdx.x * blockDim.x + threadIdx.x) >> 5;
  int lane = threadIdx.x & 31;
  if (warp >= BN + CKDIM) return;
  const float* row = (warp < BN) ? (ze + (size_t)warp * LATENT)
                                 : (books + (size_t)(warp - BN) * LATENT);
  float s = 0.f;
#pragma unroll 4
  for (int d = lane; d < LATENT; d += 32) { float v = row[d]; s += v * v; }
#pragma unroll
  for (int o = 16; o; o >>= 1) s += __shfl_xor_sync(0xffffffffu, s, o);
  if (lane == 0) { if (warp < BN) g_zn2[warp] = s; else g_bn2[warp - BN] = s; }
}

// ---------------- split: fp32 -> 2x bf16 ----------------
__global__ void k_split(const float* __restrict__ ze, const float* __restrict__ books) {
  int i = blockIdx.x * blockDim.x + threadIdx.x;
  if (i >= (BN + CKDIM) * LATENT) return;
  float x; int idx;
  __nv_bfloat16 *o1, *o2;
  if (i < BN*LATENT) { idx = i; x = ze[idx]; o1 = g_ze1; o2 = g_ze2; }
  else { idx = i - BN*LATENT; x = books[idx]; o1 = g_b1; o2 = g_b2; }
  __nv_bfloat16 h1 = __float2bfloat16(x);
  float r1 = x - __bfloat162float(h1);
  __nv_bfloat16 h2 = __float2bfloat16(r1);
  o1[idx] = h1; o2[idx] = h2;
}

// ======================= GEMM1 (HMMA bf16 split) =======================
// C[8192,5120] dot products; A=ze splits [m][k], B=books splits [n][k].
// CTA 128m x 128n, Kt=64. 8 warps: 2m x 4n grid, warp tile 64m x 32n.
#define G1_ASTR 144   // bytes per 64-bf16 row (128 + 16 pad)
#define G1_A1 0u
#define G1_A2 18432u
#define G1_B1 36864u
#define G1_B2 55296u
#define G1_SMEM 73728

__global__ __launch_bounds__(256, 1) void k_gemm1_h() {
  extern __shared__ char sm[];
  uint32_t smb = smem_u32(sm);
  int t = threadIdx.x, lane = t & 31, wid = t >> 5;
  int mb = blockIdx.x * 128, nb = blockIdx.y * 128;
  int wm = wid >> 2, wn = wid & 3;

  float acc[4][4][4];
#pragma unroll
  for (int i = 0; i < 4; i++)
#pragma unroll
    for (int j = 0; j < 4; j++)
#pragma unroll
      for (int q = 0; q < 4; q++) acc[i][j][q] = 0.f;

  for (int ch = 0; ch < 4; ch++) {
    int k0 = ch * 64;
    // stage A/B chunk (both splits): rows of 64 bf16 = 8 uint4
#pragma unroll
    for (int it = 0; it < 4; it++) {
      int idx = it * 256 + t, row = idx >> 3, q = idx & 7;
      *(uint4*)(sm + G1_A1 + row*G1_ASTR + q*16) =
          *(const uint4*)(g_ze1 + (size_t)(mb + row)*LATENT + k0 + q*8);
      *(uint4*)(sm + G1_A2 + row*G1_ASTR + q*16) =
          *(const uint4*)(g_ze2 + (size_t)(mb + row)*LATENT + k0 + q*8);
      *(uint4*)(sm + G1_B1 + row*G1_ASTR + q*16) =
          *(const uint4*)(g_b1 + (size_t)(nb + row)*LATENT + k0 + q*8);
      *(uint4*)(sm + G1_B2 + row*G1_ASTR + q*16) =
          *(const uint4*)(g_b2 + (size_t)(nb + row)*LATENT + k0 + q*8);
    }
    __syncthreads();

#pragma unroll
    for (int s = 0; s < 4; s++) {          // 4 x k16 steps
      uint32_t a1[4][4], a2[4][4];
      uint32_t arow = (uint32_t)(wm*64 + (lane & 15));
      uint32_t aoff = (uint32_t)(s*32 + (lane >> 4)*16);
#pragma unroll
      for (int fm = 0; fm < 4; fm++) {
        ldm_x4(a1[fm], smb + G1_A1 + (arow + fm*16)*G1_ASTR + aoff);
        ldm_x4(a2[fm], smb + G1_A2 + (arow + fm*16)*G1_ASTR + aoff);
      }
      uint32_t b1[4][2], b2[4][2];
      uint32_t brow = (uint32_t)(wn*32 + ((lane >> 4) * 8) + (lane & 7));
      uint32_t boff = (uint32_t)(s*32 + ((lane >> 3) & 1)*16);
#pragma unroll
      for (int fnb = 0; fnb < 2; fnb++) {
        uint32_t r[4];
        ldm_x4(r, smb + G1_B1 + (brow + fnb*16)*G1_ASTR + boff);
        b1[fnb*2][0] = r[0]; b1[fnb*2][1] = r[1];
        b1[fnb*2+1][0] = r[2]; b1[fnb*2+1][1] = r[3];
        ldm_x4(r, smb + G1_B2 + (brow + fnb*16)*G1_ASTR + boff);
        b2[fnb*2][0] = r[0]; b2[fnb*2][1] = r[1];
        b2[fnb*2+1][0] = r[2]; b2[fnb*2+1][1] = r[3];
      }
#pragma unroll
      for (int fm = 0; fm < 4; fm++)
#pragma unroll
        for (int fn = 0; fn < 4; fn++) {
          mma16816(acc[fm][fn], a1[fm], b1[fn][0], b1[fn][1]);
          mma16816(acc[fm][fn], a1[fm], b2[fn][0], b2[fn][1]);
          mma16816(acc[fm][fn], a2[fm], b1[fn][0], b1[fn][1]);
        }
    }
    __syncthreads();
  }

  // epilogue: logits = -(zn + bn - 2*dot) * pq
  float pq = g_pq[0];
  int cl = nb >> 9;               // 128-wide N tile stays in one cluster
  int kbase = nb & 511;
#pragma unroll
  for (int fm = 0; fm < 4; fm++) {
    int m0 = mb + wm*64 + fm*16 + (lane >> 2);
    int m1 = m0 + 8;
    float zn0 = g_zn2[m0], zn1 = g_zn2[m1];
    int b0i = m0 >> 8, n0i = m0 & 255;
    int b1i = m1 >> 8, n1i = m1 & 255;
    size_t ob0 = (((size_t)(b0i*NCL + cl))*NPTS + n0i)*BOOK + kbase;
    size_t ob1 = (((size_t)(b1i*NCL + cl))*NPTS + n1i)*BOOK + kbase;
#pragma unroll
    for (int fn = 0; fn < 4; fn++) {
      int kk = wn*32 + fn*8 + 2*(lane & 3);
      float2 bn = *(const float2*)&g_bn2[nb + kk];
      float2 o0, o1;
      o0.x = -(zn0 + bn.x - 2.f*acc[fm][fn][0]) * pq;
      o0.y = -(zn0 + bn.y - 2.f*acc[fm][fn][1]) * pq;
      o1.x = -(zn1 + bn.x - 2.f*acc[fm][fn][2]) * pq;
      o1.y = -(zn1 + bn.y - 2.f*acc[fm][fn][3]) * pq;
      *(float2*)&g_logits_c[ob0 + kk] = o0;
      *(float2*)&g_logits_c[ob1 + kk] = o1;
    }
  }
}

// ---------------- block reductions ----------------
template<bool IS_MAX>
__device__ __forceinline__ float blockReduce(float v, float* red) {
#pragma unroll
  for (int o = 16; o; o >>= 1) {
    float x = __shfl_xor_sync(0xffffffffu, v, o);
    v = IS_MAX ? fmaxf(v, x) : (v + x);
  }
  int w = threadIdx.x >> 5;
  __syncthreads();
  if ((threadIdx.x & 31) == 0) red[w] = v;
  __syncthreads();
  float r = red[0];
#pragma unroll
  for (int i = 1; i < 8; i++) r = IS_MAX ? fmaxf(r, red[i]) : (r + red[i]);
  return r;
}

// ---------------- K2: encoding (bf16 split output) ----------------
__global__ __launch_bounds__(256) void k2_encode(float* __restrict__ d_out,
                                                 uint32_t ke0, uint32_t ke1) {
  int b = blockIdx.x, n = blockIdx.y;
  int t = threadIdx.x;
  __shared__ float wacc[BOOK];
  __shared__ float red[8];
  __shared__ float cp[NCL];
  if (t < NCL) cp[t] = g_cprob[b*NCL + t];
  wacc[t] = 0.f; wacc[t + 256] = 0.f;
  __syncthreads();

  for (int c = 0; c < NCL; c++) {
    float cpc = cp[c];
    float L[2], y[2];
#pragma unroll
    for (int h = 0; h < 2; h++) {
      int k = t + 256*h;
      int j = ((b*NCL + c)*NPTS + n)*BOOK + k;
      float g = gumbel_from_bits(rand_bits(ke0, ke1, (uint32_t)j));
      L[h] = g_logits_c[j];
      y[h] = (L[h] + g) * 2.0f;
    }
    float m = blockReduce<true >(fmaxf(y[0], y[1]), red);
    float e0 = __expf(y[0] - m), e1 = __expf(y[1] - m);
    float s = blockReduce<false>(e0 + e1, red);
    float r = cpc / s;
    size_t enc_base = ((size_t)(b*NPTS + n))*CKDIM + c*BOOK;
    float v0 = e0 * r, v1 = e1 * r;
    __nv_bfloat16 h10 = __float2bfloat16(v0);
    __nv_bfloat16 h11 = __float2bfloat16(v1);
    g_enc1[enc_base + t]       = h10;
    g_enc1[enc_base + t + 256] = h11;
    g_enc2[enc_base + t]       = __float2bfloat16(v0 - __bfloat162float(h10));
    g_enc2[enc_base + t + 256] = __float2bfloat16(v1 - __bfloat162float(h11));
    wacc[t]       += L[0] * cpc;
    wacc[t + 256] += L[1] * cpc;
  }
  __syncthreads();

  float w0 = wacc[t], w1 = wacc[t + 256];
  float m = blockReduce<true >(fmaxf(w0, w1), red);
  float e0 = __expf(w0 - m), e1 = __expf(w1 - m);
  float s = blockReduce<false>(e0 + e1, red);
  float inv = 1.0f / s, ls = logf(s);
  int base = (b*NPTS + n)*BOOK;
  d_out[PROB_OFF + base + t]       = e0 * inv;
  d_out[PROB_OFF + base + t + 256] = e1 * inv;
  d_out[LP_OFF   + base + t]       = (w0 - m) - ls;
  d_out[LP_OFF   + base + t + 256] = (w1 - m) - ls;
}

// ======================= GEMM2 (HMMA bf16 split) =======================
// zq[8192,256] = enc[8192,5120] @ books[5120,256].
// CTA 64m x 128n, Kt=64. 8 warps: 2m x 4n, warp tile 32m x 32n.
#define G2_ASTR 144
#define G2_BSTR 272   // 128 bf16 + 8 pad
#define G2_A1 0u
#define G2_A2 9216u
#define G2_B1 18432u
#define G2_B2 35840u
#define G2_SMEM 53248

__global__ __launch_bounds__(256, 1) void k_gemm2_h(float* __restrict__ d_out) {
  extern __shared__ char sm[];
  uint32_t smb = smem_u32(sm);
  int t = threadIdx.x, lane = t & 31, wid = t >> 5;
  int mb = blockIdx.x * 64, nb = blockIdx.y * 128;
  int wm = wid >> 2, wn = wid & 3;

  float acc[2][4][4];
#pragma unroll
  for (int i = 0; i < 2; i++)
#pragma unroll
    for (int j = 0; j < 4; j++)
#pragma unroll
      for (int q = 0; q < 4; q++) acc[i][j][q] = 0.f;

  for (int ch = 0; ch < 80; ch++) {
    int k0 = ch * 64;
    // A: 64 rows x 64k (8 uint4/row), both splits
#pragma unroll
    for (int it = 0; it < 2; it++) {
      int idx = it * 256 + t, row = idx >> 3, q = idx & 7;
      *(uint4*)(sm + G2_A1 + row*G2_ASTR + q*16) =
          *(const uint4*)(g_enc1 + (size_t)(mb + row)*CKDIM + k0 + q*8);
      *(uint4*)(sm + G2_A2 + row*G2_ASTR + q*16) =
          *(const uint4*)(g_enc2 + (size_t)(mb + row)*CKDIM + k0 + q*8);
    }
    // B: 64 k-rows x 128n (16 uint4/row), both splits
#pragma unroll
    for (int it = 0; it < 4; it++) {
      int idx = it * 256 + t, row = idx >> 4, q = idx & 15;
      *(uint4*)(sm + G2_B1 + row*G2_BSTR + q*16) =
          *(const uint4*)(g_b1 + (size_t)(k0 + row)*LATENT + nb + q*8);
      *(uint4*)(sm + G2_B2 + row*G2_BSTR + q*16) =
          *(const uint4*)(g_b2 + (size_t)(k0 + row)*LATENT + nb + q*8);
    }
    __syncthreads();

#pragma unroll
    for (int s = 0; s < 4; s++) {
      uint32_t a1[2][4], a2[2][4];
      uint32_t arow = (uint32_t)(wm*32 + (lane & 15));
      uint32_t aoff = (uint32_t)(s*32 + (lane >> 4)*16);
#pragma unroll
      for (int fm = 0; fm < 2; fm++) {
        ldm_x4(a1[fm], smb + G2_A1 + (arow + fm*16)*G2_ASTR + aoff);
        ldm_x4(a2[fm], smb + G2_A2 + (arow + fm*16)*G2_ASTR + aoff);
      }
      // B via ldmatrix.trans on [k][n] rows
      uint32_t b1[4][2], b2[4][2];
      uint32_t brow = (uint32_t)(s*16 + ((lane >> 3) & 1)*8 + (lane & 7));
      uint32_t bcol = (uint32_t)(wn*32 + (lane >> 4)*8);
#pragma unroll
      for (int fnb = 0; fnb < 2; fnb++) {
        uint32_t r[4];
        ldm_x4_t(r, smb + G2_B1 + brow*G2_BSTR + (bcol + fnb*16)*2);
        b1[fnb*2][0] = r[0]; b1[fnb*2][1] = r[1];
        b1[fnb*2+1][0] = r[2]; b1[fnb*2+1][1] = r[3];
        ldm_x4_t(r, smb + G2_B2 + brow*G2_BSTR + (bcol + fnb*16)*2);
        b2[fnb*2][0] = r[0]; b2[fnb*2][1] = r[1];
        b2[fnb*2+1][0] = r[2]; b2[fnb*2+1][1] = r[3];
      }
#pragma unroll
      for (int fm = 0; fm < 2; fm++)
#pragma unroll
        for (int fn = 0; fn < 4; fn++) {
          mma16816(acc[fm][fn], a1[fm], b1[fn][0], b1[fn][1]);
          mma16816(acc[fm][fn], a1[fm], b2[fn][0], b2[fn][1]);
          mma16816(acc[fm][fn], a2[fm], b1[fn][0], b1[fn][1]);
        }
    }
    __syncthreads();
  }

#pragma unroll
  for (int fm = 0; fm < 2; fm++) {
    size_t m0 = mb + wm*32 + fm*16 + (lane >> 2);
    size_t m1 = m0 + 8;
#pragma unroll
    for (int fn = 0; fn < 4; fn++) {
      int col = nb + wn*32 + fn*8 + 2*(lane & 3);
      *(float2*)&d_out[m0*LATENT + col] = make_float2(acc[fm][fn][0], acc[fm][fn][1]);
      *(float2*)&d_out[m1*LATENT + col] = make_float2(acc[fm][fn][2], acc[fm][fn][3]);
    }
  }
}

// ---------------- launch ----------------
extern "C" void kernel_launch(void* const* d_in, const int* in_sizes, int n_in,
                              void* d_out_v, int out_size) {
  (void)in_sizes; (void)n_in; (void)out_size;
  const float* ze       = (const float*)d_in[0];
  const float* c_logits = (const float*)d_in[1];
  const float* books    = (const float*)d_in[2];
  const float* lpq      = (const float*)d_in[3];
  const float* lpqc     = (const float*)d_in[4];
  float* d_out = (float*)d_out_v;

  uint32_t kc0, kc1, ke0, ke1;
  threefry2x32(0u, 42u, 0u, 0u, kc0, kc1);
  threefry2x32(0u, 42u, 0u, 1u, ke0, ke1);

  static int attr_done = 0;
  if (!attr_done) {
    cudaFuncSetAttribute(k_gemm1_h, cudaFuncAttributeMaxDynamicSharedMemorySize, G1_SMEM);
    cudaFuncSetAttribute(k_gemm2_h, cudaFuncAttributeMaxDynamicSharedMemorySize, G2_SMEM);
    attr_done = 1;
  }

  k0_cprob<<<1, 320>>>(c_logits, lpq, lpqc, d_out, kc0, kc1);
  {
    int rows = BN + CKDIM;
    int blocks = (rows + 7) / 8;
    k_norms<<<blocks, 256>>>(ze, books);
  }
  {
    int total = (BN + CKDIM) * LATENT;
    k_split<<<(total + 255) / 256, 256>>>(ze, books);
  }
  k_gemm1_h<<<dim3(BN/128, CKDIM/128), 256, G1_SMEM>>>();
  k2_encode<<<dim3(BATCH, NPTS), 256>>>(d_out, ke0, ke1);
  k_gemm2_h<<<dim3(BN/64, LATENT/128), 256, G2_SMEM>>>(d_out);
}

// round 5
// speedup vs baseline: 3.2214x; 1.0417x over previous
#include <cuda_runtime.h>
#include <cuda_bf16.h>
#include <stdint.h>

// Problem constants
#define BATCH   32
#define NPTS    256
#define LATENT  256
#define BOOK    512
#define NCL     10
#define BN      (BATCH*NPTS)          // 8192
#define CKDIM   (NCL*BOOK)            // 5120
#define TOTALE  (BATCH*NCL*NPTS*BOOK) // 41943040

// Output layout (flattened tuple: zq, precision_q, prob, log_prob)
#define ZQ_SIZE   (BATCH*NPTS*LATENT)     // 2097152
#define PROB_OFF  (ZQ_SIZE + 1)
#define LP_OFF    (PROB_OFF + BATCH*NPTS*BOOK)

// Scratch (device globals)
__device__ __align__(16) float g_logits_c[TOTALE];   // [b,C,n,K]
__device__ __align__(16) float g_zn2[BN];
__device__ __align__(16) float g_bn2[CKDIM];
__device__ float g_cprob[BATCH*NCL];
__device__ float g_pq[1];
// bf16 2-way splits
__device__ __align__(16) __nv_bfloat16 g_ze1[BN*LATENT];
__device__ __align__(16) __nv_bfloat16 g_ze2[BN*LATENT];
__device__ __align__(16) __nv_bfloat16 g_b1[CKDIM*LATENT];
__device__ __align__(16) __nv_bfloat16 g_b2[CKDIM*LATENT];
__device__ __align__(16) __nv_bfloat16 g_enc1[(size_t)BN*CKDIM];
__device__ __align__(16) __nv_bfloat16 g_enc2[(size_t)BN*CKDIM];

// ---------------- PTX helpers ----------------
__device__ __forceinline__ uint32_t smem_u32(const void* p) {
  uint32_t a;
  asm("{ .reg .u64 t; cvta.to.shared.u64 t, %1; cvt.u32.u64 %0, t; }" : "=r"(a) : "l"(p));
  return a;
}
__device__ __forceinline__ void ldm_x4(uint32_t r[4], uint32_t addr) {
  asm volatile("ldmatrix.sync.aligned.m8n8.x4.shared.b16 {%0,%1,%2,%3}, [%4];"
               : "=r"(r[0]), "=r"(r[1]), "=r"(r[2]), "=r"(r[3]) : "r"(addr));
}
__device__ __forceinline__ void ldm_x4_t(uint32_t r[4], uint32_t addr) {
  asm volatile("ldmatrix.sync.aligned.m8n8.x4.trans.shared.b16 {%0,%1,%2,%3}, [%4];"
               : "=r"(r[0]), "=r"(r[1]), "=r"(r[2]), "=r"(r[3]) : "r"(addr));
}
__device__ __forceinline__ void mma16816(float d[4], const uint32_t a[4],
                                         const uint32_t b0, const uint32_t b1) {
  asm volatile(
    "mma.sync.aligned.m16n8k16.row.col.f32.bf16.bf16.f32 "
    "{%0,%1,%2,%3}, {%4,%5,%6,%7}, {%8,%9}, {%0,%1,%2,%3};"
    : "+f"(d[0]), "+f"(d[1]), "+f"(d[2]), "+f"(d[3])
    : "r"(a[0]), "r"(a[1]), "r"(a[2]), "r"(a[3]), "r"(b0), "r"(b1));
}
__device__ __forceinline__ void cp16(uint32_t smem_addr, const void* gptr) {
  asm volatile("cp.async.cg.shared.global [%0], [%1], 16;"
               :: "r"(smem_addr), "l"(gptr) : "memory");
}
#define CP_COMMIT()  asm volatile("cp.async.commit_group;" ::: "memory")
#define CP_WAIT(n)   asm volatile("cp.async.wait_group %0;" :: "n"(n) : "memory")

// ---------------- threefry2x32 (JAX exact) ----------------
__host__ __device__ __forceinline__ void threefry2x32(
    uint32_t k0, uint32_t k1, uint32_t x0, uint32_t x1,
    uint32_t& o0, uint32_t& o1) {
  uint32_t ks2 = 0x1BD11BDAu ^ k0 ^ k1;
  x0 += k0; x1 += k1;
#define TF_ROT(r) { x0 += x1; x1 = (x1 << (r)) | (x1 >> (32-(r))); x1 ^= x0; }
  TF_ROT(13) TF_ROT(15) TF_ROT(26) TF_ROT(6)
  x0 += k1;  x1 += ks2 + 1u;
  TF_ROT(17) TF_ROT(29) TF_ROT(16) TF_ROT(24)
  x0 += ks2; x1 += k0 + 2u;
  TF_ROT(13) TF_ROT(15) TF_ROT(26) TF_ROT(6)
  x0 += k0;  x1 += k1 + 3u;
  TF_ROT(17) TF_ROT(29) TF_ROT(16) TF_ROT(24)
  x0 += k1;  x1 += ks2 + 4u;
  TF_ROT(13) TF_ROT(15) TF_ROT(26) TF_ROT(6)
  x0 += ks2; x1 += k0 + 5u;
#undef TF_ROT
  o0 = x0; o1 = x1;
}
__device__ __forceinline__ float unit_from_bits(uint32_t bits) {
  return __uint_as_float((bits >> 9) | 0x3f800000u) - 1.0f;
}
// Accurate inner log (rel error near u~1 corrupts gumbel-max winners);
// fast outer log (absolute error only).
__device__ __forceinline__ float gumbel_from_bits(uint32_t bits) {
  float u = unit_from_bits(bits);
  float inner = logf(u + 1e-10f);
  return -__logf(1e-10f - inner);
}
__device__ __forceinline__ uint32_t rand_bits(uint32_t k0, uint32_t k1, uint32_t j) {
  uint32_t o0, o1;
  threefry2x32(k0, k1, 0u, j, o0, o1);
  return o0 ^ o1;
}

// ---------------- K0 ----------------
__global__ void k0_cprob(const float* __restrict__ c_logits,
                         const float* __restrict__ lpq,
                         const float* __restrict__ lpqc,
                         float* __restrict__ d_out,
                         uint32_t kc0, uint32_t kc1) {
  __shared__ float gsh[BATCH*NCL];
  int t = threadIdx.x;
  if (t < BATCH*NCL) gsh[t] = gumbel_from_bits(rand_bits(kc0, kc1, (uint32_t)t));
  float pq  = 0.5f / fmaxf(1.0f + expf(lpq[0]),  1e-10f);
  float pqc = 0.5f / fmaxf(1.0f + expf(lpqc[0]), 1e-10f);
  if (t == 0) { g_pq[0] = pq; d_out[ZQ_SIZE] = pq; }
  __syncthreads();
  if (t < BATCH) {
    float y[NCL];
    float m = -3.4e38f;
#pragma unroll
    for (int c = 0; c < NCL; c++) {
      y[c] = (c_logits[t*NCL + c] * pqc + gsh[t*NCL + c]) * 2.0f;
      m = fmaxf(m, y[c]);
    }
    float s = 0.f;
#pragma unroll
    for (int c = 0; c < NCL; c++) { y[c] = expf(y[c] - m); s += y[c]; }
    float inv = 1.0f / s;
#pragma unroll
    for (int c = 0; c < NCL; c++) g_cprob[t*NCL + c] = y[c] * inv;
  }
}

// ---------------- norms ----------------
__global__ void k_norms(const float* __restrict__ ze, const float* __restrict__ books) {
  int warp = (blockIdx.x * blockDim.x + threadIdx.x) >> 5;
  int lane = threadIdx.x & 31;
  if (warp >= BN + CKDIM) return;
  const float* row = (warp < BN) ? (ze + (size_t)warp * LATENT)
                                 : (books + (size_t)(warp - BN) * LATENT);
  float s = 0.f;
#pragma unroll 4
  for (int d = lane; d < LATENT; d += 32) { float v = row[d]; s += v * v; }
#pragma unroll
  for (int o = 16; o; o >>= 1) s += __shfl_xor_sync(0xffffffffu, s, o);
  if (lane == 0) { if (warp < BN) g_zn2[warp] = s; else g_bn2[warp - BN] = s; }
}

// ---------------- split: fp32 -> 2x bf16 ----------------
__global__ void k_split(const float* __restrict__ ze, const float* __restrict__ books) {
  int i = blockIdx.x * blockDim.x + threadIdx.x;
  if (i >= (BN + CKDIM) * LATENT) return;
  float x; int idx;
  __nv_bfloat16 *o1, *o2;
  if (i < BN*LATENT) { idx = i; x = ze[idx]; o1 = g_ze1; o2 = g_ze2; }
  else { idx = i - BN*LATENT; x = books[idx]; o1 = g_b1; o2 = g_b2; }
  __nv_bfloat16 h1 = __float2bfloat16(x);
  float r1 = x - __bfloat162float(h1);
  __nv_bfloat16 h2 = __float2bfloat16(r1);
  o1[idx] = h1; o2[idx] = h2;
}

// ======================= GEMM1 (HMMA bf16 split, cp.async double-buffered) ====
// CTA 128m x 128n, Kt=64, 4 chunks. 8 warps: 2m x 4n, warp tile 64m x 32n.
#define G1_ASTR 144   // bytes per 64-bf16 row (128 + 16 pad)
#define G1_A1 0u
#define G1_A2 18432u
#define G1_B1 36864u
#define G1_B2 55296u
#define G1_STAGE 73728u
#define G1_SMEM (2*73728)

__device__ __forceinline__ void g1_load_chunk(uint32_t smb, int st, int mb, int nb,
                                              int k0, int t) {
  uint32_t sb = smb + (uint32_t)st * G1_STAGE;
#pragma unroll
  for (int it = 0; it < 4; it++) {
    int idx = it * 256 + t, row = idx >> 3, q = idx & 7;
    uint32_t roff = (uint32_t)(row * G1_ASTR + q * 16);
    cp16(sb + G1_A1 + roff, g_ze1 + (size_t)(mb + row)*LATENT + k0 + q*8);
    cp16(sb + G1_A2 + roff, g_ze2 + (size_t)(mb + row)*LATENT + k0 + q*8);
    cp16(sb + G1_B1 + roff, g_b1  + (size_t)(nb + row)*LATENT + k0 + q*8);
    cp16(sb + G1_B2 + roff, g_b2  + (size_t)(nb + row)*LATENT + k0 + q*8);
  }
  CP_COMMIT();
}

__global__ __launch_bounds__(256, 1) void k_gemm1_h() {
  extern __shared__ char sm[];
  uint32_t smb = smem_u32(sm);
  int t = threadIdx.x, lane = t & 31, wid = t >> 5;
  int mb = blockIdx.x * 128, nb = blockIdx.y * 128;
  int wm = wid >> 2, wn = wid & 3;

  float acc[4][4][4];
#pragma unroll
  for (int i = 0; i < 4; i++)
#pragma unroll
    for (int j = 0; j < 4; j++)
#pragma unroll
      for (int q = 0; q < 4; q++) acc[i][j][q] = 0.f;

  g1_load_chunk(smb, 0, mb, nb, 0, t);

  for (int ch = 0; ch < 4; ch++) {
    if (ch < 3) {
      g1_load_chunk(smb, (ch + 1) & 1, mb, nb, (ch + 1) * 64, t);
      CP_WAIT(1);
    } else {
      CP_WAIT(0);
    }
    __syncthreads();
    uint32_t sb = smb + (uint32_t)(ch & 1) * G1_STAGE;

#pragma unroll
    for (int s = 0; s < 4; s++) {          // 4 x k16 steps
      uint32_t a1[4][4], a2[4][4];
      uint32_t arow = (uint32_t)(wm*64 + (lane & 15));
      uint32_t aoff = (uint32_t)(s*32 + (lane >> 4)*16);
#pragma unroll
      for (int fm = 0; fm < 4; fm++) {
        ldm_x4(a1[fm], sb + G1_A1 + (arow + fm*16)*G1_ASTR + aoff);
        ldm_x4(a2[fm], sb + G1_A2 + (arow + fm*16)*G1_ASTR + aoff);
      }
      uint32_t b1[4][2], b2[4][2];
      uint32_t brow = (uint32_t)(wn*32 + ((lane >> 4) * 8) + (lane & 7));
      uint32_t boff = (uint32_t)(s*32 + ((lane >> 3) & 1)*16);
#pragma unroll
      for (int fnb = 0; fnb < 2; fnb++) {
        uint32_t r[4];
        ldm_x4(r, sb + G1_B1 + (brow + fnb*16)*G1_ASTR + boff);
        b1[fnb*2][0] = r[0]; b1[fnb*2][1] = r[1];
        b1[fnb*2+1][0] = r[2]; b1[fnb*2+1][1] = r[3];
        ldm_x4(r, sb + G1_B2 + (brow + fnb*16)*G1_ASTR + boff);
        b2[fnb*2][0] = r[0]; b2[fnb*2][1] = r[1];
        b2[fnb*2+1][0] = r[2]; b2[fnb*2+1][1] = r[3];
      }
#pragma unroll
      for (int fm = 0; fm < 4; fm++)
#pragma unroll
        for (int fn = 0; fn < 4; fn++) {
          mma16816(acc[fm][fn], a1[fm], b1[fn][0], b1[fn][1]);
          mma16816(acc[fm][fn], a1[fm], b2[fn][0], b2[fn][1]);
          mma16816(acc[fm][fn], a2[fm], b1[fn][0], b1[fn][1]);
        }
    }
    __syncthreads();
  }

  // epilogue: logits = -(zn + bn - 2*dot) * pq
  float pq = g_pq[0];
  int cl = nb >> 9;
  int kbase = nb & 511;
#pragma unroll
  for (int fm = 0; fm < 4; fm++) {
    int m0 = mb + wm*64 + fm*16 + (lane >> 2);
    int m1 = m0 + 8;
    float zn0 = g_zn2[m0], zn1 = g_zn2[m1];
    int b0i = m0 >> 8, n0i = m0 & 255;
    int b1i = m1 >> 8, n1i = m1 & 255;
    size_t ob0 = (((size_t)(b0i*NCL + cl))*NPTS + n0i)*BOOK + kbase;
    size_t ob1 = (((size_t)(b1i*NCL + cl))*NPTS + n1i)*BOOK + kbase;
#pragma unroll
    for (int fn = 0; fn < 4; fn++) {
      int kk = wn*32 + fn*8 + 2*(lane & 3);
      float2 bn = *(const float2*)&g_bn2[nb + kk];
      float2 o0, o1;
      o0.x = -(zn0 + bn.x - 2.f*acc[fm][fn][0]) * pq;
      o0.y = -(zn0 + bn.y - 2.f*acc[fm][fn][1]) * pq;
      o1.x = -(zn1 + bn.x - 2.f*acc[fm][fn][2]) * pq;
      o1.y = -(zn1 + bn.y - 2.f*acc[fm][fn][3]) * pq;
      *(float2*)&g_logits_c[ob0 + kk] = o0;
      *(float2*)&g_logits_c[ob1 + kk] = o1;
    }
  }
}

// ---------------- block reductions ----------------
template<bool IS_MAX>
__device__ __forceinline__ float blockReduce(float v, float* red) {
#pragma unroll
  for (int o = 16; o; o >>= 1) {
    float x = __shfl_xor_sync(0xffffffffu, v, o);
    v = IS_MAX ? fmaxf(v, x) : (v + x);
  }
  int w = threadIdx.x >> 5;
  __syncthreads();
  if ((threadIdx.x & 31) == 0) red[w] = v;
  __syncthreads();
  float r = red[0];
#pragma unroll
  for (int i = 1; i < 8; i++) r = IS_MAX ? fmaxf(r, red[i]) : (r + red[i]);
  return r;
}

// ---------------- K2: encoding (bf16 split output) ----------------
__global__ __launch_bounds__(256) void k2_encode(float* __restrict__ d_out,
                                                 uint32_t ke0, uint32_t ke1) {
  int b = blockIdx.x, n = blockIdx.y;
  int t = threadIdx.x;
  __shared__ float wacc[BOOK];
  __shared__ float red[8];
  __shared__ float cp[NCL];
  if (t < NCL) cp[t] = g_cprob[b*NCL + t];
  wacc[t] = 0.f; wacc[t + 256] = 0.f;
  __syncthreads();

  for (int c = 0; c < NCL; c++) {
    float cpc = cp[c];
    float L[2], y[2];
#pragma unroll
    for (int h = 0; h < 2; h++) {
      int k = t + 256*h;
      int j = ((b*NCL + c)*NPTS + n)*BOOK + k;
      float g = gumbel_from_bits(rand_bits(ke0, ke1, (uint32_t)j));
      L[h] = g_logits_c[j];
      y[h] = (L[h] + g) * 2.0f;
    }
    float m = blockReduce<true >(fmaxf(y[0], y[1]), red);
    float e0 = __expf(y[0] - m), e1 = __expf(y[1] - m);
    float s = blockReduce<false>(e0 + e1, red);
    float r = cpc / s;
    size_t enc_base = ((size_t)(b*NPTS + n))*CKDIM + c*BOOK;
    float v0 = e0 * r, v1 = e1 * r;
    __nv_bfloat16 h10 = __float2bfloat16(v0);
    __nv_bfloat16 h11 = __float2bfloat16(v1);
    g_enc1[enc_base + t]       = h10;
    g_enc1[enc_base + t + 256] = h11;
    g_enc2[enc_base + t]       = __float2bfloat16(v0 - __bfloat162float(h10));
    g_enc2[enc_base + t + 256] = __float2bfloat16(v1 - __bfloat162float(h11));
    wacc[t]       += L[0] * cpc;
    wacc[t + 256] += L[1] * cpc;
  }
  __syncthreads();

  float w0 = wacc[t], w1 = wacc[t + 256];
  float m = blockReduce<true >(fmaxf(w0, w1), red);
  float e0 = __expf(w0 - m), e1 = __expf(w1 - m);
  float s = blockReduce<false>(e0 + e1, red);
  float inv = 1.0f / s, ls = logf(s);
  int base = (b*NPTS + n)*BOOK;
  d_out[PROB_OFF + base + t]       = e0 * inv;
  d_out[PROB_OFF + base + t + 256] = e1 * inv;
  d_out[LP_OFF   + base + t]       = (w0 - m) - ls;
  d_out[LP_OFF   + base + t + 256] = (w1 - m) - ls;
}

// ======================= GEMM2 (HMMA bf16 split, cp.async double-buffered) ====
// zq[8192,256] = enc[8192,5120] @ books[5120,256].
// CTA 64m x 128n, Kt=64, 80 chunks. 8 warps: 2m x 4n, warp tile 32m x 32n.
#define G2_ASTR 144
#define G2_BSTR 272   // 128 bf16 + 8 pad
#define G2_A1 0u
#define G2_A2 9216u
#define G2_B1 18432u
#define G2_B2 35840u
#define G2_STAGE 53248u
#define G2_SMEM (2*53248)

__device__ __forceinline__ void g2_load_chunk(uint32_t smb, int st, int mb, int nb,
                                              int k0, int t) {
  uint32_t sb = smb + (uint32_t)st * G2_STAGE;
#pragma unroll
  for (int it = 0; it < 2; it++) {
    int idx = it * 256 + t, row = idx >> 3, q = idx & 7;
    uint32_t roff = (uint32_t)(row * G2_ASTR + q * 16);
    cp16(sb + G2_A1 + roff, g_enc1 + (size_t)(mb + row)*CKDIM + k0 + q*8);
    cp16(sb + G2_A2 + roff, g_enc2 + (size_t)(mb + row)*CKDIM + k0 + q*8);
  }
#pragma unroll
  for (int it = 0; it < 4; it++) {
    int idx = it * 256 + t, row = idx >> 4, q = idx & 15;
    uint32_t roff = (uint32_t)(row * G2_BSTR + q * 16);
    cp16(sb + G2_B1 + roff, g_b1 + (size_t)(k0 + row)*LATENT + nb + q*8);
    cp16(sb + G2_B2 + roff, g_b2 + (size_t)(k0 + row)*LATENT + nb + q*8);
  }
  CP_COMMIT();
}

__global__ __launch_bounds__(256, 1) void k_gemm2_h(float* __restrict__ d_out) {
  extern __shared__ char sm[];
  uint32_t smb = smem_u32(sm);
  int t = threadIdx.x, lane = t & 31, wid = t >> 5;
  int mb = blockIdx.x * 64, nb = blockIdx.y * 128;
  int wm = wid >> 2, wn = wid & 3;

  float acc[2][4][4];
#pragma unroll
  for (int i = 0; i < 2; i++)
#pragma unroll
    for (int j = 0; j < 4; j++)
#pragma unroll
      for (int q = 0; q < 4; q++) acc[i][j][q] = 0.f;

  g2_load_chunk(smb, 0, mb, nb, 0, t);

  for (int ch = 0; ch < 80; ch++) {
    if (ch < 79) {
      g2_load_chunk(smb, (ch + 1) & 1, mb, nb, (ch + 1) * 64, t);
      CP_WAIT(1);
    } else {
      CP_WAIT(0);
    }
    __syncthreads();
    uint32_t sb = smb + (uint32_t)(ch & 1) * G2_STAGE;

#pragma unroll
    for (int s = 0; s < 4; s++) {
      uint32_t a1[2][4], a2[2][4];
      uint32_t arow = (uint32_t)(wm*32 + (lane & 15));
      uint32_t aoff = (uint32_t)(s*32 + (lane >> 4)*16);
#pragma unroll
      for (int fm = 0; fm < 2; fm++) {
        ldm_x4(a1[fm], sb + G2_A1 + (arow + fm*16)*G2_ASTR + aoff);
        ldm_x4(a2[fm], sb + G2_A2 + (arow + fm*16)*G2_ASTR + aoff);
      }
      uint32_t b1[4][2], b2[4][2];
      uint32_t brow = (uint32_t)(s*16 + ((lane >> 3) & 1)*8 + (lane & 7));
      uint32_t bcol = (uint32_t)(wn*32 + (lane >> 4)*8);
#pragma unroll
      for (int fnb = 0; fnb < 2; fnb++) {
        uint32_t r[4];
        ldm_x4_t(r, sb + G2_B1 + brow*G2_BSTR + (bcol + fnb*16)*2);
        b1[fnb*2][0] = r[0]; b1[fnb*2][1] = r[1];
        b1[fnb*2+1][0] = r[2]; b1[fnb*2+1][1] = r[3];
        ldm_x4_t(r, sb + G2_B2 + brow*G2_BSTR + (bcol + fnb*16)*2);
        b2[fnb*2][0] = r[0]; b2[fnb*2][1] = r[1];
        b2[fnb*2+1][0] = r[2]; b2[fnb*2+1][1] = r[3];
      }
#pragma unroll
      for (int fm = 0; fm < 2; fm++)
#pragma unroll
        for (int fn = 0; fn < 4; fn++) {
          mma16816(acc[fm][fn], a1[fm], b1[fn][0], b1[fn][1]);
          mma16816(acc[fm][fn], a1[fm], b2[fn][0], b2[fn][1]);
          mma16816(acc[fm][fn], a2[fm], b1[fn][0], b1[fn][1]);
        }
    }
    __syncthreads();
  }

#pragma unroll
  for (int fm = 0; fm < 2; fm++) {
    size_t m0 = mb + wm*32 + fm*16 + (lane >> 2);
    size_t m1 = m0 + 8;
#pragma unroll
    for (int fn = 0; fn < 4; fn++) {
      int col = nb + wn*32 + fn*8 + 2*(lane & 3);
      *(float2*)&d_out[m0*LATENT + col] = make_float2(acc[fm][fn][0], acc[fm][fn][1]);
      *(float2*)&d_out[m1*LATENT + col] = make_float2(acc[fm][fn][2], acc[fm][fn][3]);
    }
  }
}

// ---------------- launch ----------------
extern "C" void kernel_launch(void* const* d_in, const int* in_sizes, int n_in,
                              void* d_out_v, int out_size) {
  (void)in_sizes; (void)n_in; (void)out_size;
  const float* ze       = (const float*)d_in[0];
  const float* c_logits = (const float*)d_in[1];
  const float* books    = (const float*)d_in[2];
  const float* lpq      = (const float*)d_in[3];
  const float* lpqc     = (const float*)d_in[4];
  float* d_out = (float*)d_out_v;

  uint32_t kc0, kc1, ke0, ke1;
  threefry2x32(0u, 42u, 0u, 0u, kc0, kc1);
  threefry2x32(0u, 42u, 0u, 1u, ke0, ke1);

  static int attr_done = 0;
  if (!attr_done) {
    cudaFuncSetAttribute(k_gemm1_h, cudaFuncAttributeMaxDynamicSharedMemorySize, G1_SMEM);
    cudaFuncSetAttribute(k_gemm2_h, cudaFuncAttributeMaxDynamicSharedMemorySize, G2_SMEM);
    attr_done = 1;
  }

  k0_cprob<<<1, 320>>>(c_logits, lpq, lpqc, d_out, kc0, kc1);
  {
    int rows = BN + CKDIM;
    int blocks = (rows + 7) / 8;
    k_norms<<<blocks, 256>>>(ze, books);
  }
  {
    int total = (BN + CKDIM) * LATENT;
    k_split<<<(total + 255) / 256, 256>>>(ze, books);
  }
  k_gemm1_h<<<dim3(BN/128, CKDIM/128), 256, G1_SMEM>>>();
  k2_encode<<<dim3(BATCH, NPTS), 256>>>(d_out, ke0, ke1);
  k_gemm2_h<<<dim3(BN/64, LATENT/128), 256, G2_SMEM>>>(d_out);
}

// round 6
// speedup vs baseline: 3.3302x; 1.0338x over previous
#include <cuda_runtime.h>
#include <cuda_bf16.h>
#include <stdint.h>

// Problem constants
#define BATCH   32
#define NPTS    256
#define LATENT  256
#define BOOK    512
#define NCL     10
#define BN      (BATCH*NPTS)          // 8192
#define CKDIM   (NCL*BOOK)            // 5120
#define TOTALE  (BATCH*NCL*NPTS*BOOK) // 41943040

// Output layout (flattened tuple: zq, precision_q, prob, log_prob)
#define ZQ_SIZE   (BATCH*NPTS*LATENT)     // 2097152
#define PROB_OFF  (ZQ_SIZE + 1)
#define LP_OFF    (PROB_OFF + BATCH*NPTS*BOOK)

// Scratch (device globals)
__device__ __align__(16) float g_logits_c[TOTALE];   // [b,C,n,K]
__device__ __align__(16) float g_zn2[BN];
__device__ __align__(16) float g_bn2[CKDIM];
__device__ float g_cprob[BATCH*NCL];
__device__ float g_pq[1];
// bf16 2-way splits
__device__ __align__(16) __nv_bfloat16 g_ze1[BN*LATENT];
__device__ __align__(16) __nv_bfloat16 g_ze2[BN*LATENT];
__device__ __align__(16) __nv_bfloat16 g_b1[CKDIM*LATENT];
__device__ __align__(16) __nv_bfloat16 g_b2[CKDIM*LATENT];
__device__ __align__(16) __nv_bfloat16 g_enc1[(size_t)BN*CKDIM];
__device__ __align__(16) __nv_bfloat16 g_enc2[(size_t)BN*CKDIM];

// ---------------- PTX helpers ----------------
__device__ __forceinline__ uint32_t smem_u32(const void* p) {
  uint32_t a;
  asm("{ .reg .u64 t; cvta.to.shared.u64 t, %1; cvt.u32.u64 %0, t; }" : "=r"(a) : "l"(p));
  return a;
}
__device__ __forceinline__ void ldm_x4(uint32_t r[4], uint32_t addr) {
  asm volatile("ldmatrix.sync.aligned.m8n8.x4.shared.b16 {%0,%1,%2,%3}, [%4];"
               : "=r"(r[0]), "=r"(r[1]), "=r"(r[2]), "=r"(r[3]) : "r"(addr));
}
__device__ __forceinline__ void ldm_x4_t(uint32_t r[4], uint32_t addr) {
  asm volatile("ldmatrix.sync.aligned.m8n8.x4.trans.shared.b16 {%0,%1,%2,%3}, [%4];"
               : "=r"(r[0]), "=r"(r[1]), "=r"(r[2]), "=r"(r[3]) : "r"(addr));
}
__device__ __forceinline__ void mma16816(float d[4], const uint32_t a[4],
                                         const uint32_t b0, const uint32_t b1) {
  asm volatile(
    "mma.sync.aligned.m16n8k16.row.col.f32.bf16.bf16.f32 "
    "{%0,%1,%2,%3}, {%4,%5,%6,%7}, {%8,%9}, {%0,%1,%2,%3};"
    : "+f"(d[0]), "+f"(d[1]), "+f"(d[2]), "+f"(d[3])
    : "r"(a[0]), "r"(a[1]), "r"(a[2]), "r"(a[3]), "r"(b0), "r"(b1));
}
__device__ __forceinline__ void cp16(uint32_t smem_addr, const void* gptr) {
  asm volatile("cp.async.cg.shared.global [%0], [%1], 16;"
               :: "r"(smem_addr), "l"(gptr) : "memory");
}
#define CP_COMMIT()  asm volatile("cp.async.commit_group;" ::: "memory")
#define CP_WAIT(n)   asm volatile("cp.async.wait_group %0;" :: "n"(n) : "memory")

// ---------------- threefry2x32 (JAX exact) ----------------
__host__ __device__ __forceinline__ void threefry2x32(
    uint32_t k0, uint32_t k1, uint32_t x0, uint32_t x1,
    uint32_t& o0, uint32_t& o1) {
  uint32_t ks2 = 0x1BD11BDAu ^ k0 ^ k1;
  x0 += k0; x1 += k1;
#define TF_ROT(r) { x0 += x1; x1 = (x1 << (r)) | (x1 >> (32-(r))); x1 ^= x0; }
  TF_ROT(13) TF_ROT(15) TF_ROT(26) TF_ROT(6)
  x0 += k1;  x1 += ks2 + 1u;
  TF_ROT(17) TF_ROT(29) TF_ROT(16) TF_ROT(24)
  x0 += ks2; x1 += k0 + 2u;
  TF_ROT(13) TF_ROT(15) TF_ROT(26) TF_ROT(6)
  x0 += k0;  x1 += k1 + 3u;
  TF_ROT(17) TF_ROT(29) TF_ROT(16) TF_ROT(24)
  x0 += k1;  x1 += ks2 + 4u;
  TF_ROT(13) TF_ROT(15) TF_ROT(26) TF_ROT(6)
  x0 += ks2; x1 += k0 + 5u;
#undef TF_ROT
  o0 = x0; o1 = x1;
}
__device__ __forceinline__ float unit_from_bits(uint32_t bits) {
  return __uint_as_float((bits >> 9) | 0x3f800000u) - 1.0f;
}
// Accurate inner log (rel error near u~1 corrupts gumbel-max winners);
// fast outer log (absolute error only).
__device__ __forceinline__ float gumbel_from_bits(uint32_t bits) {
  float u = unit_from_bits(bits);
  float inner = logf(u + 1e-10f);
  return -__logf(1e-10f - inner);
}
__device__ __forceinline__ uint32_t rand_bits(uint32_t k0, uint32_t k1, uint32_t j) {
  uint32_t o0, o1;
  threefry2x32(k0, k1, 0u, j, o0, o1);
  return o0 ^ o1;
}

// ---------------- K0 ----------------
__global__ void k0_cprob(const float* __restrict__ c_logits,
                         const float* __restrict__ lpq,
                         const float* __restrict__ lpqc,
                         float* __restrict__ d_out,
                         uint32_t kc0, uint32_t kc1) {
  __shared__ float gsh[BATCH*NCL];
  int t = threadIdx.x;
  if (t < BATCH*NCL) gsh[t] = gumbel_from_bits(rand_bits(kc0, kc1, (uint32_t)t));
  float pq  = 0.5f / fmaxf(1.0f + expf(lpq[0]),  1e-10f);
  float pqc = 0.5f / fmaxf(1.0f + expf(lpqc[0]), 1e-10f);
  if (t == 0) { g_pq[0] = pq; d_out[ZQ_SIZE] = pq; }
  __syncthreads();
  if (t < BATCH) {
    float y[NCL];
    float m = -3.4e38f;
#pragma unroll
    for (int c = 0; c < NCL; c++) {
      y[c] = (c_logits[t*NCL + c] * pqc + gsh[t*NCL + c]) * 2.0f;
      m = fmaxf(m, y[c]);
    }
    float s = 0.f;
#pragma unroll
    for (int c = 0; c < NCL; c++) { y[c] = expf(y[c] - m); s += y[c]; }
    float inv = 1.0f / s;
#pragma unroll
    for (int c = 0; c < NCL; c++) g_cprob[t*NCL + c] = y[c] * inv;
  }
}

// ---------------- norms ----------------
__global__ void k_norms(const float* __restrict__ ze, const float* __restrict__ books) {
  int warp = (blockIdx.x * blockDim.x + threadIdx.x) >> 5;
  int lane = threadIdx.x & 31;
  if (warp >= BN + CKDIM) return;
  const float* row = (warp < BN) ? (ze + (size_t)warp * LATENT)
                                 : (books + (size_t)(warp - BN) * LATENT);
  float s = 0.f;
#pragma unroll 4
  for (int d = lane; d < LATENT; d += 32) { float v = row[d]; s += v * v; }
#pragma unroll
  for (int o = 16; o; o >>= 1) s += __shfl_xor_sync(0xffffffffu, s, o);
  if (lane == 0) { if (warp < BN) g_zn2[warp] = s; else g_bn2[warp - BN] = s; }
}

// ---------------- split: fp32 -> 2x bf16 ----------------
__global__ void k_split(const float* __restrict__ ze, const float* __restrict__ books) {
  int i = blockIdx.x * blockDim.x + threadIdx.x;
  if (i >= (BN + CKDIM) * LATENT) return;
  float x; int idx;
  __nv_bfloat16 *o1, *o2;
  if (i < BN*LATENT) { idx = i; x = ze[idx]; o1 = g_ze1; o2 = g_ze2; }
  else { idx = i - BN*LATENT; x = books[idx]; o1 = g_b1; o2 = g_b2; }
  __nv_bfloat16 h1 = __float2bfloat16(x);
  float r1 = x - __bfloat162float(h1);
  __nv_bfloat16 h2 = __float2bfloat16(r1);
  o1[idx] = h1; o2[idx] = h2;
}

// ======== GEMM1 (HMMA bf16 split, cp.async dbuf, 2 CTA/SM) ========
// CTA 128m x 64n, Kt=64, 4 chunks. 8 warps: 4m x 2n, warp tile 32m x 32n.
#define G1_ASTR 144   // bytes per 64-bf16 row (128 + 16 pad)
#define G1_A1 0u
#define G1_A2 18432u
#define G1_B1 36864u
#define G1_B2 46080u
#define G1_STAGE 55296u
#define G1_SMEM (2*55296)

__device__ __forceinline__ void g1_load_chunk(uint32_t smb, int st, int mb, int nb,
                                              int k0, int t) {
  uint32_t sb = smb + (uint32_t)st * G1_STAGE;
#pragma unroll
  for (int it = 0; it < 4; it++) {        // A: 128 rows x 8 uint4, both splits
    int idx = it * 256 + t, row = idx >> 3, q = idx & 7;
    uint32_t roff = (uint32_t)(row * G1_ASTR + q * 16);
    cp16(sb + G1_A1 + roff, g_ze1 + (size_t)(mb + row)*LATENT + k0 + q*8);
    cp16(sb + G1_A2 + roff, g_ze2 + (size_t)(mb + row)*LATENT + k0 + q*8);
  }
#pragma unroll
  for (int it = 0; it < 2; it++) {        // B: 64 rows x 8 uint4, both splits
    int idx = it * 256 + t, row = idx >> 3, q = idx & 7;
    uint32_t roff = (uint32_t)(row * G1_ASTR + q * 16);
    cp16(sb + G1_B1 + roff, g_b1 + (size_t)(nb + row)*LATENT + k0 + q*8);
    cp16(sb + G1_B2 + roff, g_b2 + (size_t)(nb + row)*LATENT + k0 + q*8);
  }
  CP_COMMIT();
}

__global__ __launch_bounds__(256, 2) void k_gemm1_h() {
  extern __shared__ char sm[];
  uint32_t smb = smem_u32(sm);
  int t = threadIdx.x, lane = t & 31, wid = t >> 5;
  int mb = blockIdx.x * 128, nb = blockIdx.y * 64;
  int wm = wid >> 1, wn = wid & 1;

  float acc[2][4][4];
#pragma unroll
  for (int i = 0; i < 2; i++)
#pragma unroll
    for (int j = 0; j < 4; j++)
#pragma unroll
      for (int q = 0; q < 4; q++) acc[i][j][q] = 0.f;

  g1_load_chunk(smb, 0, mb, nb, 0, t);

  for (int ch = 0; ch < 4; ch++) {
    if (ch < 3) {
      g1_load_chunk(smb, (ch + 1) & 1, mb, nb, (ch + 1) * 64, t);
      CP_WAIT(1);
    } else {
      CP_WAIT(0);
    }
    __syncthreads();
    uint32_t sb = smb + (uint32_t)(ch & 1) * G1_STAGE;

#pragma unroll
    for (int s = 0; s < 4; s++) {          // 4 x k16 steps
      uint32_t a1[2][4], a2[2][4];
      uint32_t arow = (uint32_t)(wm*32 + (lane & 15));
      uint32_t aoff = (uint32_t)(s*32 + (lane >> 4)*16);
#pragma unroll
      for (int fm = 0; fm < 2; fm++) {
        ldm_x4(a1[fm], sb + G1_A1 + (arow + fm*16)*G1_ASTR + aoff);
        ldm_x4(a2[fm], sb + G1_A2 + (arow + fm*16)*G1_ASTR + aoff);
      }
      uint32_t b1[4][2], b2[4][2];
      uint32_t brow = (uint32_t)(wn*32 + ((lane >> 4) * 8) + (lane & 7));
      uint32_t boff = (uint32_t)(s*32 + ((lane >> 3) & 1)*16);
#pragma unroll
      for (int fnb = 0; fnb < 2; fnb++) {
        uint32_t r[4];
        ldm_x4(r, sb + G1_B1 + (brow + fnb*16)*G1_ASTR + boff);
        b1[fnb*2][0] = r[0]; b1[fnb*2][1] = r[1];
        b1[fnb*2+1][0] = r[2]; b1[fnb*2+1][1] = r[3];
        ldm_x4(r, sb + G1_B2 + (brow + fnb*16)*G1_ASTR + boff);
        b2[fnb*2][0] = r[0]; b2[fnb*2][1] = r[1];
        b2[fnb*2+1][0] = r[2]; b2[fnb*2+1][1] = r[3];
      }
#pragma unroll
      for (int fm = 0; fm < 2; fm++)
#pragma unroll
        for (int fn = 0; fn < 4; fn++) {
          mma16816(acc[fm][fn], a1[fm], b1[fn][0], b1[fn][1]);
          mma16816(acc[fm][fn], a1[fm], b2[fn][0], b2[fn][1]);
          mma16816(acc[fm][fn], a2[fm], b1[fn][0], b1[fn][1]);
        }
    }
    __syncthreads();
  }

  // epilogue: logits = -(zn + bn - 2*dot) * pq
  float pq = g_pq[0];
  int cl = nb >> 9;               // 64-wide N tile stays in one cluster
  int kbase = nb & 511;
#pragma unroll
  for (int fm = 0; fm < 2; fm++) {
    int m0 = mb + wm*32 + fm*16 + (lane >> 2);
    int m1 = m0 + 8;
    float zn0 = g_zn2[m0], zn1 = g_zn2[m1];
    int b0i = m0 >> 8, n0i = m0 & 255;
    int b1i = m1 >> 8, n1i = m1 & 255;
    size_t ob0 = (((size_t)(b0i*NCL + cl))*NPTS + n0i)*BOOK + kbase;
    size_t ob1 = (((size_t)(b1i*NCL + cl))*NPTS + n1i)*BOOK + kbase;
#pragma unroll
    for (int fn = 0; fn < 4; fn++) {
      int kk = wn*32 + fn*8 + 2*(lane & 3);
      float2 bn = *(const float2*)&g_bn2[nb + kk];
      float2 o0, o1;
      o0.x = -(zn0 + bn.x - 2.f*acc[fm][fn][0]) * pq;
      o0.y = -(zn0 + bn.y - 2.f*acc[fm][fn][1]) * pq;
      o1.x = -(zn1 + bn.x - 2.f*acc[fm][fn][2]) * pq;
      o1.y = -(zn1 + bn.y - 2.f*acc[fm][fn][3]) * pq;
      *(float2*)&g_logits_c[ob0 + kk] = o0;
      *(float2*)&g_logits_c[ob1 + kk] = o1;
    }
  }
}

// ---------------- block reductions ----------------
template<bool IS_MAX>
__device__ __forceinline__ float blockReduce(float v, float* red) {
#pragma unroll
  for (int o = 16; o; o >>= 1) {
    float x = __shfl_xor_sync(0xffffffffu, v, o);
    v = IS_MAX ? fmaxf(v, x) : (v + x);
  }
  int w = threadIdx.x >> 5;
  __syncthreads();
  if ((threadIdx.x & 31) == 0) red[w] = v;
  __syncthreads();
  float r = red[0];
#pragma unroll
  for (int i = 1; i < 8; i++) r = IS_MAX ? fmaxf(r, red[i]) : (r + red[i]);
  return r;
}

// ---------------- K2: encoding (bf16 split output) ----------------
__global__ __launch_bounds__(256) void k2_encode(float* __restrict__ d_out,
                                                 uint32_t ke0, uint32_t ke1) {
  int b = blockIdx.x, n = blockIdx.y;
  int t = threadIdx.x;
  __shared__ float wacc[BOOK];
  __shared__ float red[8];
  __shared__ float cp[NCL];
  if (t < NCL) cp[t] = g_cprob[b*NCL + t];
  wacc[t] = 0.f; wacc[t + 256] = 0.f;
  __syncthreads();

  for (int c = 0; c < NCL; c++) {
    float cpc = cp[c];
    float L[2], y[2];
#pragma unroll
    for (int h = 0; h < 2; h++) {
      int k = t + 256*h;
      int j = ((b*NCL + c)*NPTS + n)*BOOK + k;
      float g = gumbel_from_bits(rand_bits(ke0, ke1, (uint32_t)j));
      L[h] = g_logits_c[j];
      y[h] = (L[h] + g) * 2.0f;
    }
    float m = blockReduce<true >(fmaxf(y[0], y[1]), red);
    float e0 = __expf(y[0] - m), e1 = __expf(y[1] - m);
    float s = blockReduce<false>(e0 + e1, red);
    float r = cpc / s;
    size_t enc_base = ((size_t)(b*NPTS + n))*CKDIM + c*BOOK;
    float v0 = e0 * r, v1 = e1 * r;
    __nv_bfloat16 h10 = __float2bfloat16(v0);
    __nv_bfloat16 h11 = __float2bfloat16(v1);
    g_enc1[enc_base + t]       = h10;
    g_enc1[enc_base + t + 256] = h11;
    g_enc2[enc_base + t]       = __float2bfloat16(v0 - __bfloat162float(h10));
    g_enc2[enc_base + t + 256] = __float2bfloat16(v1 - __bfloat162float(h11));
    wacc[t]       += L[0] * cpc;
    wacc[t + 256] += L[1] * cpc;
  }
  __syncthreads();

  float w0 = wacc[t], w1 = wacc[t + 256];
  float m = blockReduce<true >(fmaxf(w0, w1), red);
  float e0 = __expf(w0 - m), e1 = __expf(w1 - m);
  float s = blockReduce<false>(e0 + e1, red);
  float inv = 1.0f / s, ls = logf(s);
  int base = (b*NPTS + n)*BOOK;
  d_out[PROB_OFF + base + t]       = e0 * inv;
  d_out[PROB_OFF + base + t + 256] = e1 * inv;
  d_out[LP_OFF   + base + t]       = (w0 - m) - ls;
  d_out[LP_OFF   + base + t + 256] = (w1 - m) - ls;
}

// ======== GEMM2 (HMMA bf16 split, cp.async dbuf, 2 CTA/SM) ========
// zq[8192,256] = enc[8192,5120] @ books[5120,256].
// CTA 64m x 128n, Kt=64, 80 chunks. 8 warps: 2m x 4n, warp tile 32m x 32n.
#define G2_ASTR 144
#define G2_BSTR 272   // 128 bf16 + 8 pad
#define G2_A1 0u
#define G2_A2 9216u
#define G2_B1 18432u
#define G2_B2 35840u
#define G2_STAGE 53248u
#define G2_SMEM (2*53248)

__device__ __forceinline__ void g2_load_chunk(uint32_t smb, int st, int mb, int nb,
                                              int k0, int t) {
  uint32_t sb = smb + (uint32_t)st * G2_STAGE;
#pragma unroll
  for (int it = 0; it < 2; it++) {
    int idx = it * 256 + t, row = idx >> 3, q = idx & 7;
    uint32_t roff = (uint32_t)(row * G2_ASTR + q * 16);
    cp16(sb + G2_A1 + roff, g_enc1 + (size_t)(mb + row)*CKDIM + k0 + q*8);
    cp16(sb + G2_A2 + roff, g_enc2 + (size_t)(mb + row)*CKDIM + k0 + q*8);
  }
#pragma unroll
  for (int it = 0; it < 4; it++) {
    int idx = it * 256 + t, row = idx >> 4, q = idx & 15;
    uint32_t roff = (uint32_t)(row * G2_BSTR + q * 16);
    cp16(sb + G2_B1 + roff, g_b1 + (size_t)(k0 + row)*LATENT + nb + q*8);
    cp16(sb + G2_B2 + roff, g_b2 + (size_t)(k0 + row)*LATENT + nb + q*8);
  }
  CP_COMMIT();
}

__global__ __launch_bounds__(256, 2) void k_gemm2_h(float* __restrict__ d_out) {
  extern __shared__ char sm[];
  uint32_t smb = smem_u32(sm);
  int t = threadIdx.x, lane = t & 31, wid = t >> 5;
  int mb = blockIdx.x * 64, nb = blockIdx.y * 128;
  int wm = wid >> 2, wn = wid & 3;

  float acc[2][4][4];
#pragma unroll
  for (int i = 0; i < 2; i++)
#pragma unroll
    for (int j = 0; j < 4; j++)
#pragma unroll
      for (int q = 0; q < 4; q++) acc[i][j][q] = 0.f;

  g2_load_chunk(smb, 0, mb, nb, 0, t);

  for (int ch = 0; ch < 80; ch++) {
    if (ch < 79) {
      g2_load_chunk(smb, (ch + 1) & 1, mb, nb, (ch + 1) * 64, t);
      CP_WAIT(1);
    } else {
      CP_WAIT(0);
    }
    __syncthreads();
    uint32_t sb = smb + (uint32_t)(ch & 1) * G2_STAGE;

#pragma unroll
    for (int s = 0; s < 4; s++) {
      uint32_t a1[2][4], a2[2][4];
      uint32_t arow = (uint32_t)(wm*32 + (lane & 15));
      uint32_t aoff = (uint32_t)(s*32 + (lane >> 4)*16);
#pragma unroll
      for (int fm = 0; fm < 2; fm++) {
        ldm_x4(a1[fm], sb + G2_A1 + (arow + fm*16)*G2_ASTR + aoff);
        ldm_x4(a2[fm], sb + G2_A2 + (arow + fm*16)*G2_ASTR + aoff);
      }
      uint32_t b1[4][2], b2[4][2];
      uint32_t brow = (uint32_t)(s*16 + ((lane >> 3) & 1)*8 + (lane & 7));
      uint32_t bcol = (uint32_t)(wn*32 + (lane >> 4)*8);
#pragma unroll
      for (int fnb = 0; fnb < 2; fnb++) {
        uint32_t r[4];
        ldm_x4_t(r, sb + G2_B1 + brow*G2_BSTR + (bcol + fnb*16)*2);
        b1[fnb*2][0] = r[0]; b1[fnb*2][1] = r[1];
        b1[fnb*2+1][0] = r[2]; b1[fnb*2+1][1] = r[3];
        ldm_x4_t(r, sb + G2_B2 + brow*G2_BSTR + (bcol + fnb*16)*2);
        b2[fnb*2][0] = r[0]; b2[fnb*2][1] = r[1];
        b2[fnb*2+1][0] = r[2]; b2[fnb*2+1][1] = r[3];
      }
#pragma unroll
      for (int fm = 0; fm < 2; fm++)
#pragma unroll
        for (int fn = 0; fn < 4; fn++) {
          mma16816(acc[fm][fn], a1[fm], b1[fn][0], b1[fn][1]);
          mma16816(acc[fm][fn], a1[fm], b2[fn][0], b2[fn][1]);
          mma16816(acc[fm][fn], a2[fm], b1[fn][0], b1[fn][1]);
        }
    }
    __syncthreads();
  }

#pragma unroll
  for (int fm = 0; fm < 2; fm++) {
    size_t m0 = mb + wm*32 + fm*16 + (lane >> 2);
    size_t m1 = m0 + 8;
#pragma unroll
    for (int fn = 0; fn < 4; fn++) {
      int col = nb + wn*32 + fn*8 + 2*(lane & 3);
      *(float2*)&d_out[m0*LATENT + col] = make_float2(acc[fm][fn][0], acc[fm][fn][1]);
      *(float2*)&d_out[m1*LATENT + col] = make_float2(acc[fm][fn][2], acc[fm][fn][3]);
    }
  }
}

// ---------------- launch ----------------
extern "C" void kernel_launch(void* const* d_in, const int* in_sizes, int n_in,
                              void* d_out_v, int out_size) {
  (void)in_sizes; (void)n_in; (void)out_size;
  const float* ze       = (const float*)d_in[0];
  const float* c_logits = (const float*)d_in[1];
  const float* books    = (const float*)d_in[2];
  const float* lpq      = (const float*)d_in[3];
  const float* lpqc     = (const float*)d_in[4];
  float* d_out = (float*)d_out_v;

  uint32_t kc0, kc1, ke0, ke1;
  threefry2x32(0u, 42u, 0u, 0u, kc0, kc1);
  threefry2x32(0u, 42u, 0u, 1u, ke0, ke1);

  static int attr_done = 0;
  if (!attr_done) {
    cudaFuncSetAttribute(k_gemm1_h, cudaFuncAttributeMaxDynamicSharedMemorySize, G1_SMEM);
    cudaFuncSetAttribute(k_gemm2_h, cudaFuncAttributeMaxDynamicSharedMemorySize, G2_SMEM);
    attr_done = 1;
  }

  k0_cprob<<<1, 320>>>(c_logits, lpq, lpqc, d_out, kc0, kc1);
  {
    int rows = BN + CKDIM;
    int blocks = (rows + 7) / 8;
    k_norms<<<blocks, 256>>>(ze, books);
  }
  {
    int total = (BN + CKDIM) * LATENT;
    k_split<<<(total + 255) / 256, 256>>>(ze, books);
  }
  k_gemm1_h<<<dim3(BN/128, CKDIM/64), 256, G1_SMEM>>>();
  k2_encode<<<dim3(BATCH, NPTS), 256>>>(d_out, ke0, ke1);
  k_gemm2_h<<<dim3(BN/64, LATENT/128), 256, G2_SMEM>>>(d_out);
}